// round 12
// baseline (speedup 1.0000x reference)
#include <cuda_runtime.h>
#include <cuda_bf16.h>
#include <math.h>

#define BB 4
#define SS 2048
#define DD 64
#define NN 2048
#define NTOK (BB*SS)
#define CT 64
#define NCH (SS/CT)
#define NCHT (BB*NCH)

// -------- static device scratch (no allocations allowed) ----------
__device__ float g_k[NTOK*DD];
__device__ float g_q[NTOK*DD];
__device__ float g_v[NTOK*DD];
__device__ float g_nu[NTOK*DD];
__device__ float g_pw[NTOK*4];
__device__ float g_us[NTOK];
__device__ float g_outf[NTOK*DD];
__device__ float g_outs[NTOK*DD];
__device__ float g_pqf[NTOK*DD];
__device__ float g_pqs[NTOK*DD];
__device__ float g_kk[NCHT*CT*CT];
__device__ float g_qx[NCHT*CT*CT];
__device__ float g_W [2*NCHT*CT*CT];
__device__ float g_A2[2*NCHT*CT*CT];
__device__ float g_gate[NTOK];
__device__ float g_outpre[NTOK*DD];
__device__ float g_a[NTOK*DD];

__device__ __forceinline__ float gelu_exact(float x){
    return 0.5f*x*(1.0f + erff(x*0.70710678118654752f));
}
__device__ __forceinline__ float dot4(float4 a, float4 b){
    return a.x*b.x + a.y*b.y + a.z*b.z + a.w*b.w;
}
__device__ __forceinline__ void mma16816(float* c, const unsigned* a, const unsigned* b){
    asm volatile(
        "mma.sync.aligned.m16n8k16.row.col.f32.bf16.bf16.f32 "
        "{%0,%1,%2,%3}, {%4,%5,%6,%7}, {%8,%9}, {%0,%1,%2,%3};"
        : "+f"(c[0]), "+f"(c[1]), "+f"(c[2]), "+f"(c[3])
        : "r"(a[0]), "r"(a[1]), "r"(a[2]), "r"(a[3]), "r"(b[0]), "r"(b[1]));
}

// ---------------------------------------------------------------------------
// Kernel 1a: tensor-core projections (k, v, q) via split-bf16 mma.
// grid (64 row-tiles, 3 segments), 256 thr (8 warps). Tile 128x64, KC=32.
// x = xh + xl (bf16), W = wh + wl; acc = xh*wh + xh*wl + xl*wh (fp32 acc).
// seg0: k=l2norm(.), seg1: v, seg2: q=l2norm(.).
// ---------------------------------------------------------------------------
#define KC 32
#define ASTR 40
__global__ void __launch_bounds__(256,2) projmma_kernel(
    const float* __restrict__ x,
    const float* __restrict__ Wk, const float* __restrict__ Wv,
    const float* __restrict__ Wq)
{
    __shared__ __align__(16) __nv_bfloat16 Ah[128][ASTR];
    __shared__ __align__(16) __nv_bfloat16 Al[128][ASTR];
    __shared__ __align__(16) __nv_bfloat16 Bh[64][ASTR];
    __shared__ __align__(16) __nv_bfloat16 Bl[64][ASTR];

    const int seg  = blockIdx.y;
    const int row0 = blockIdx.x * 128;
    const float* __restrict__ W = (seg==0)?Wk:(seg==1)?Wv:Wq;

    const int tid  = threadIdx.x;
    const int warp = tid >> 5;
    const int lane = tid & 31;
    const int g = lane >> 2;
    const int t = lane & 3;
    const int wrow = warp * 16;

    float C[8][4];
    #pragma unroll
    for (int n=0;n<8;n++)
        #pragma unroll
        for (int j=0;j<4;j++) C[n][j]=0.f;

    for (int kb = 0; kb < NN; kb += KC){
        // stage x tile: 128 rows x 32 cols, split to bf16 hi/lo
        #pragma unroll
        for (int l=0;l<4;l++){
            int idx = tid + l*256;          // f4 index; 1024 total
            int row = idx >> 3, c4 = (idx & 7)*4;
            float4 xv = *(const float4*)&x[(long)(row0+row)*NN + kb + c4];
            float xs[4] = {xv.x,xv.y,xv.z,xv.w};
            #pragma unroll
            for (int j=0;j<4;j++){
                __nv_bfloat16 h = __float2bfloat16(xs[j]);
                Ah[row][c4+j] = h;
                Al[row][c4+j] = __float2bfloat16(xs[j] - __bfloat162float(h));
            }
        }
        // stage W tile: 32 rows x 64 cols, transposed [n][k], split hi/lo
        #pragma unroll
        for (int l=0;l<2;l++){
            int idx = tid + l*256;          // f4 index; 512 total
            int kk = idx >> 4, c4 = (idx & 15)*4;
            float4 wv = *(const float4*)&W[(long)(kb+kk)*DD + c4];
            float ws[4] = {wv.x,wv.y,wv.z,wv.w};
            #pragma unroll
            for (int j=0;j<4;j++){
                __nv_bfloat16 h = __float2bfloat16(ws[j]);
                Bh[c4+j][kk] = h;
                Bl[c4+j][kk] = __float2bfloat16(ws[j] - __bfloat162float(h));
            }
        }
        __syncthreads();

        #pragma unroll
        for (int ks=0; ks<2; ks++){
            const int k16 = ks*16;
            unsigned ahf[4], alf[4];
            ahf[0] = *(const unsigned*)&Ah[wrow+g  ][k16+t*2];
            ahf[1] = *(const unsigned*)&Ah[wrow+g+8][k16+t*2];
            ahf[2] = *(const unsigned*)&Ah[wrow+g  ][k16+8+t*2];
            ahf[3] = *(const unsigned*)&Ah[wrow+g+8][k16+8+t*2];
            alf[0] = *(const unsigned*)&Al[wrow+g  ][k16+t*2];
            alf[1] = *(const unsigned*)&Al[wrow+g+8][k16+t*2];
            alf[2] = *(const unsigned*)&Al[wrow+g  ][k16+8+t*2];
            alf[3] = *(const unsigned*)&Al[wrow+g+8][k16+8+t*2];
            #pragma unroll
            for (int nt=0; nt<8; nt++){
                const int n = nt*8 + g;
                unsigned bhf[2], blf[2];
                bhf[0] = *(const unsigned*)&Bh[n][k16+t*2];
                bhf[1] = *(const unsigned*)&Bh[n][k16+8+t*2];
                blf[0] = *(const unsigned*)&Bl[n][k16+t*2];
                blf[1] = *(const unsigned*)&Bl[n][k16+8+t*2];
                mma16816(C[nt], ahf, bhf);
                mma16816(C[nt], ahf, blf);
                mma16816(C[nt], alf, bhf);
            }
        }
        __syncthreads();
    }

    // epilogue
    float* dst = (seg==0)? g_k : (seg==1)? g_v : g_q;
    const long rlo = row0 + wrow + g;
    const long rhi = rlo + 8;
    if (seg == 1){
        #pragma unroll
        for (int nt=0; nt<8; nt++){
            *(float2*)&dst[rlo*DD + nt*8 + t*2] = make_float2(C[nt][0], C[nt][1]);
            *(float2*)&dst[rhi*DD + nt*8 + t*2] = make_float2(C[nt][2], C[nt][3]);
        }
    } else {
        float sl = 0.f, sh = 0.f;
        #pragma unroll
        for (int nt=0; nt<8; nt++){
            sl += C[nt][0]*C[nt][0] + C[nt][1]*C[nt][1];
            sh += C[nt][2]*C[nt][2] + C[nt][3]*C[nt][3];
        }
        const unsigned FULL = 0xffffffffu;
        sl += __shfl_xor_sync(FULL, sl, 1); sl += __shfl_xor_sync(FULL, sl, 2);
        sh += __shfl_xor_sync(FULL, sh, 1); sh += __shfl_xor_sync(FULL, sh, 2);
        float il = 1.0f / fmaxf(sqrtf(sl), 1e-12f);
        float ih = 1.0f / fmaxf(sqrtf(sh), 1e-12f);
        #pragma unroll
        for (int nt=0; nt<8; nt++){
            *(float2*)&dst[rlo*DD + nt*8 + t*2] = make_float2(C[nt][0]*il, C[nt][1]*il);
            *(float2*)&dst[rhi*DD + nt*8 + t*2] = make_float2(C[nt][2]*ih, C[nt][3]*ih);
        }
    }
}

// ---------------------------------------------------------------------------
// Kernel 1b: importance gate in exact fp32 (sharp threshold -> no bf16 risk).
// us = ((gelu(x@ir_w1 + b1) @ ir_w2) + b2) > 0. grid 32 blocks per half.
// ---------------------------------------------------------------------------
__global__ void __launch_bounds__(256,2) irproj_kernel(
    const float* __restrict__ x, const float* __restrict__ ir_w1,
    const float* __restrict__ ir_b1, const float* __restrict__ ir_w2,
    const float* __restrict__ ir_b2, int row_off)
{
    __shared__ __align__(16) float As[2][16][132];
    __shared__ __align__(16) float Bs[2][16][68];
    const int row0 = row_off + blockIdx.x * 128;
    const int tid = threadIdx.x;
    const int tr = tid >> 4;
    const int tc = tid & 15;

    float acc[8][4];
    #pragma unroll
    for (int i=0;i<8;i++)
        #pragma unroll
        for (int j=0;j<4;j++) acc[i][j]=0.f;

    float4 ra[2]; float4 rb;
    {
        #pragma unroll
        for (int j=0;j<2;j++){
            int s = tid*2 + j;
            int m = s >> 2, k4 = s & 3;
            ra[j] = *(const float4*)&x[(long)(row0+m)*NN + k4*4];
        }
        { int kk = tid >> 4, c4 = tid & 15;
          rb = *(const float4*)&ir_w1[(long)kk*DD + c4*4]; }
        #pragma unroll
        for (int j=0;j<2;j++){
            int s = tid*2+j; int m = s>>2, k4 = s&3;
            As[0][k4*4+0][m]=ra[j].x; As[0][k4*4+1][m]=ra[j].y;
            As[0][k4*4+2][m]=ra[j].z; As[0][k4*4+3][m]=ra[j].w;
        }
        { int kk=tid>>4, c4=tid&15; *(float4*)&Bs[0][kk][c4*4] = rb; }
    }
    __syncthreads();

    for (int c=0; c<128; c++){
        const int buf = c & 1;
        if (c+1 < 128){
            int k0 = (c+1)*16;
            #pragma unroll
            for (int j=0;j<2;j++){
                int s = tid*2 + j; int m = s>>2, k4 = s&3;
                ra[j] = *(const float4*)&x[(long)(row0+m)*NN + k0 + k4*4];
            }
            int kk = tid>>4, c4 = tid&15;
            rb = *(const float4*)&ir_w1[(long)(k0+kk)*DD + c4*4];
        }
        #pragma unroll
        for (int kk=0; kk<16; kk++){
            float4 a0 = *(float4*)&As[buf][kk][tr*8];
            float4 a1 = *(float4*)&As[buf][kk][tr*8+4];
            float4 bb = *(float4*)&Bs[buf][kk][tc*4];
            float am[8] = {a0.x,a0.y,a0.z,a0.w,a1.x,a1.y,a1.z,a1.w};
            float bn[4] = {bb.x,bb.y,bb.z,bb.w};
            #pragma unroll
            for (int i=0;i<8;i++)
                #pragma unroll
                for (int j=0;j<4;j++) acc[i][j] = fmaf(am[i], bn[j], acc[i][j]);
        }
        if (c+1 < 128){
            int nb = (c+1)&1;
            #pragma unroll
            for (int j=0;j<2;j++){
                int s = tid*2+j; int m=s>>2,k4=s&3;
                As[nb][k4*4+0][m]=ra[j].x; As[nb][k4*4+1][m]=ra[j].y;
                As[nb][k4*4+2][m]=ra[j].z; As[nb][k4*4+3][m]=ra[j].w;
            }
            int kk=tid>>4,c4=tid&15;
            *(float4*)&Bs[nb][kk][c4*4]=rb;
        }
        __syncthreads();
    }

    const unsigned FULL = 0xffffffffu;
    float b1v[4], w2v[4];
    #pragma unroll
    for (int j=0;j<4;j++){ b1v[j]=ir_b1[tc*4+j]; w2v[j]=ir_w2[tc*4+j]; }
    float b2 = ir_b2[0];
    #pragma unroll
    for (int i=0;i<8;i++){
        float p = 0.f;
        #pragma unroll
        for (int j=0;j<4;j++) p += gelu_exact(acc[i][j]+b1v[j]) * w2v[j];
        p += __shfl_xor_sync(FULL, p, 1);
        p += __shfl_xor_sync(FULL, p, 2);
        p += __shfl_xor_sync(FULL, p, 4);
        p += __shfl_xor_sync(FULL, p, 8);
        if (tc==0){
            long row = row0 + tr*8 + i;
            g_us[row] = (p + b2) > 0.f ? 1.f : 0.f;
        }
    }
}

// ---------------------------------------------------------------------------
// Kernel 2: per-chunk Gram matrices.
// ---------------------------------------------------------------------------
__global__ void __launch_bounds__(256) chunkdots_kernel(){
    __shared__ __align__(16) float Ks[CT][68];
    __shared__ __align__(16) float Qs[CT][68];
    const int p = blockIdx.x;
    const long t0 = (long)p*CT;
    const int tid = threadIdx.x;
    const float4* kp = (const float4*)(g_k + t0*DD);
    const float4* qp = (const float4*)(g_q + t0*DD);
    #pragma unroll
    for (int l=0;l<4;l++){
        int f4 = tid + l*256;
        int row = f4 >> 4, col = (f4 & 15)*4;
        *(float4*)&Ks[row][col] = kp[f4];
        *(float4*)&Qs[row][col] = qp[f4];
    }
    __syncthreads();
    #pragma unroll
    for (int m=0;m<16;m++){
        int idx = tid + m*256;
        int i = idx >> 6, j = idx & 63;
        float sk = 0.f, sq = 0.f;
        #pragma unroll
        for (int r4=0;r4<16;r4++){
            float4 kj = *(float4*)&Ks[j][r4*4];
            float4 ki = *(float4*)&Ks[i][r4*4];
            float4 qi = *(float4*)&Qs[i][r4*4];
            sk += dot4(ki,kj);
            sq += dot4(qi,kj);
        }
        g_kk[(long)p*4096 + idx] = sk;
        g_qx[(long)p*4096 + idx] = sq;
    }
}

// ---------------------------------------------------------------------------
// Kernel 3: per chunk-state: build L, invert (I+L) -> W, build A2.
// ---------------------------------------------------------------------------
__global__ void __launch_bounds__(64) prep_kernel(
    const float* __restrict__ fa_p, const float* __restrict__ sa_p)
{
    __shared__ float L[CT][65];
    __shared__ float W[CT][65];
    __shared__ float apow[CT];
    __shared__ float gi[CT];
    const int p = blockIdx.x;
    const int st = blockIdx.y;
    const long t0 = (long)p*CT;
    const int tid = threadIdx.x;
    const float a = st ? *sa_p : *fa_p;
    const float oa = 1.0f - a;
    if (tid == 0){
        float w = 1.f;
        for (int i=0;i<CT;i++){ apow[i] = w; w *= a; }
    }
    gi[tid] = st ? oa*g_us[t0+tid] : oa;
    __syncthreads();
    const long base = (long)p*4096;
    const long obase = ((long)st*NCHT + p)*4096;
    for (int f = tid; f < 4096; f += 64){
        int i = f >> 6, j = f & 63;
        float dec = (j < i) ? apow[i-1-j] : 0.f;
        L[i][j] = dec * gi[i] * g_kk[base+f];
        g_A2[obase+f] = dec * g_qx[base+f];
    }
    __syncthreads();
    {
        const int j = tid;
        for (int i=0;i<CT;i++) W[i][j] = (i==j) ? 1.f : 0.f;
        for (int i=j+1;i<CT;i++){
            float s = 0.f;
            for (int k=j;k<i;k++) s = fmaf(L[i][k], W[k][j], s);
            W[i][j] = -s;
        }
    }
    __syncthreads();
    for (int f = tid; f < 4096; f += 64)
        g_W[obase+f] = W[f>>6][f&63];
}

// ---------------------------------------------------------------------------
// Kernel 4: chunked scan. grid (16, 4, 2), 256 thr.
// ---------------------------------------------------------------------------
__global__ void __launch_bounds__(256,1) scan_chunk_kernel(
    const float* __restrict__ fa_p, const float* __restrict__ sa_p)
{
    __shared__ __align__(16) float Ks[CT][68];
    __shared__ __align__(16) float Ss[CT][68];
    __shared__ __align__(16) float H [4][68];
    __shared__ __align__(16) float T1[4][68];
    __shared__ __align__(16) float Cc[4][68];
    __shared__ __align__(16) float QHs[4][68];
    __shared__ float apow[CT];

    const int cg = blockIdx.x;
    const int b  = blockIdx.y;
    const int st = blockIdx.z;
    const int tid = threadIdx.x;
    const int i = tid >> 2;
    const int c = tid & 3;
    const int colg = cg*4 + c;
    const float a = st ? *sa_p : *fa_p;
    const float oa = 1.0f - a;
    float* __restrict__ outp = st ? g_outs : g_outf;
    float* __restrict__ pqp  = st ? g_pqs  : g_pqf;

    if (tid == 0){
        float w = 1.f;
        for (int t=0;t<CT;t++){ apow[t] = w; w *= a; }
    }
    H[c][i] = 0.f;
    __syncthreads();
    const float a64 = apow[63]*a;

    for (int ch = 0; ch < NCH; ch++){
        const int  pidx = b*NCH + ch;
        const long t0   = (long)pidx*CT;
        const long wbase = ((long)st*NCHT + pidx)*4096;

        {
            const float4* kp = (const float4*)(g_k + t0*DD);
            const float4* qp = (const float4*)(g_q + t0*DD);
            #pragma unroll
            for (int l=0;l<4;l++){
                int f4 = tid + l*256;
                int row = f4 >> 4, col = (f4 & 15)*4;
                *(float4*)&Ks[row][col] = kp[f4];
                *(float4*)&Ss[row][col] = qp[f4];
            }
        }
        __syncthreads();

        {
            float akh = 0.f, aqh = 0.f;
            #pragma unroll
            for (int r4=0;r4<16;r4++){
                float4 h4 = *(float4*)&H [c][r4*4];
                float4 k4 = *(float4*)&Ks[i][r4*4];
                float4 q4 = *(float4*)&Ss[i][r4*4];
                akh += dot4(k4,h4);
                aqh += dot4(q4,h4);
            }
            float giv = st ? oa*g_us[t0+i] : oa;
            float v   = g_v[(t0+i)*DD + colg];
            T1[c][i]  = giv*(v - apow[i]*akh);
            QHs[c][i] = aqh;
        }
        __syncthreads();

        {
            const float4* wp = (const float4*)(g_W + wbase);
            #pragma unroll
            for (int l=0;l<4;l++){
                int f4 = tid + l*256;
                int row = f4 >> 4, col = (f4 & 15)*4;
                *(float4*)&Ss[row][col] = wp[f4];
            }
        }
        __syncthreads();

        {
            float s = 0.f;
            #pragma unroll
            for (int j4=0;j4<16;j4++){
                float4 w4 = *(float4*)&Ss[i][j4*4];
                float4 r4 = *(float4*)&T1[c][j4*4];
                s += dot4(w4,r4);
            }
            Cc[c][i] = s;
        }
        __syncthreads();

        {
            const float4* ap = (const float4*)(g_A2 + wbase);
            #pragma unroll
            for (int l=0;l<4;l++){
                int f4 = tid + l*256;
                int row = f4 >> 4, col = (f4 & 15)*4;
                *(float4*)&Ss[row][col] = ap[f4];
            }
        }
        __syncthreads();

        {
            float s = 0.f;
            #pragma unroll
            for (int j4=0;j4<16;j4++){
                float4 a4 = *(float4*)&Ss[i][j4*4];
                float4 c4 = *(float4*)&Cc[c][j4*4];
                s += dot4(a4,c4);
            }
            float ci = Cc[c][i];
            float pq = fmaf(apow[i], QHs[c][i], s);
            float qk = g_qx[(long)pidx*4096 + i*65];
            float o  = fmaf(qk, ci, a*pq);
            pqp [(t0+i)*DD + colg] = pq;
            outp[(t0+i)*DD + colg] = o;
            T1[c][i] = apow[63-i]*ci;
        }
        __syncthreads();

        {
            float h = a64*H[c][i];
            #pragma unroll
            for (int j=0;j<CT;j++)
                h = fmaf(Ks[j][i], T1[c][j], h);
            H[c][i] = h;
        }
        __syncthreads();
    }
}

// ---------------------------------------------------------------------------
// Kernel 5: pw = softmax(x @ pw_w + pw_b). warp per token.
// ---------------------------------------------------------------------------
__global__ void __launch_bounds__(256) pw_kernel(
    const float* __restrict__ x, const float* __restrict__ pw_w,
    const float* __restrict__ pw_b)
{
    __shared__ __align__(16) float pwT[3][2048];
    const int tid = threadIdx.x;
    for (int idx = tid; idx < 3*2048; idx += 256){
        int i = idx/3, cc = idx - i*3;
        pwT[cc][i] = pw_w[idx];
    }
    __syncthreads();
    const int warp = tid>>5, lane = tid&31;
    const float b0 = pw_b[0], b1 = pw_b[1], b2 = pw_b[2];
    const unsigned FULL = 0xffffffffu;
    for (int it8 = 0; it8 < 8; it8++){
        long tok = (long)blockIdx.x*64 + warp*8 + it8;
        const float* xr = x + tok*NN;
        float a0=0.f,a1=0.f,a2=0.f;
        #pragma unroll
        for (int it=0; it<16; it++){
            int off = it*128 + lane*4;
            float4 xv = *(const float4*)&xr[off];
            float4 w0 = *(const float4*)&pwT[0][off];
            float4 w1 = *(const float4*)&pwT[1][off];
            float4 w2 = *(const float4*)&pwT[2][off];
            a0 += dot4(xv,w0);
            a1 += dot4(xv,w1);
            a2 += dot4(xv,w2);
        }
        #pragma unroll
        for (int d=1; d<32; d<<=1){
            a0 += __shfl_xor_sync(FULL, a0, d);
            a1 += __shfl_xor_sync(FULL, a1, d);
            a2 += __shfl_xor_sync(FULL, a2, d);
        }
        if (lane==0){
            float l0=a0+b0, l1=a1+b1, l2=a2+b2;
            float m = fmaxf(l0, fmaxf(l1,l2));
            float e0=expf(l0-m), e1=expf(l1-m), e2=expf(l2-m);
            float inv = 1.0f/(e0+e1+e2);
            g_pw[tok*4+0]=e0*inv; g_pw[tok*4+1]=e1*inv;
            g_pw[tok*4+2]=e2*inv; g_pw[tok*4+3]=0.f;
        }
    }
}

// ---------------------------------------------------------------------------
// Kernel 6: nu = gelu(v @ nm_w1 + b1) @ nm_w2 + b2. warp per token.
// ---------------------------------------------------------------------------
__global__ void __launch_bounds__(256) nu_kernel(
    const float* __restrict__ nm_w1, const float* __restrict__ nm_b1,
    const float* __restrict__ nm_w2, const float* __restrict__ nm_b2)
{
    __shared__ float W1s[64*128];
    __shared__ float hs[8][128];
    __shared__ float vs[8][64];
    const int tid = threadIdx.x;
    for (int i = tid; i < 64*128; i += 256) W1s[i] = nm_w1[i];
    long tok0 = (long)blockIdx.x*8;
    for (int i = tid; i < 8*64; i += 256){
        int t = i>>6, r = i&63;
        vs[t][r] = g_v[(tok0+t)*DD + r];
    }
    __syncthreads();
    const int warp = tid>>5, lane = tid&31;
    #pragma unroll
    for (int ii=0;ii<4;ii++){
        int i = lane + ii*32;
        float a = nm_b1[i];
        #pragma unroll 8
        for (int r=0;r<64;r++) a = fmaf(vs[warp][r], W1s[r*128+i], a);
        hs[warp][i] = gelu_exact(a);
    }
    __syncwarp();
    #pragma unroll
    for (int jj=0;jj<2;jj++){
        int j = lane + jj*32;
        float a = nm_b2[j];
        #pragma unroll 8
        for (int i=0;i<128;i++) a = fmaf(hs[warp][i], __ldg(&nm_w2[i*64+j]), a);
        g_nu[(tok0+warp)*DD + j] = a;
    }
}

// ---------------------------------------------------------------------------
// Kernel 7: gate from reconstructed error. warp per token.
// ---------------------------------------------------------------------------
__global__ void __launch_bounds__(256) gate_kernel(){
    const int tid = threadIdx.x;
    const int warp = tid>>5, lane = tid&31;
    long tok = (long)blockIdx.x*8 + warp;
    float s = 0.f;
    #pragma unroll
    for (int h=0; h<2; h++){
        int c = lane + h*32;
        float v  = g_v[tok*DD + c];
        float pf = g_pqf[tok*DD + c];
        float ps = g_pqs[tok*DD + c];
        float e = v - 0.5f*(pf + ps);
        s += e*e;
    }
    const unsigned FULL = 0xffffffffu;
    #pragma unroll
    for (int d=1; d<32; d<<=1) s += __shfl_xor_sync(FULL,s,d);
    if (lane==0){
        g_gate[tok] = (s > 0.84729871f) ? 0.1f : 0.0f;
    }
}

// ---------------------------------------------------------------------------
// Kernel 8: ns scan + pw combine, unroll-8 with batched prefetch.
// ---------------------------------------------------------------------------
__global__ void __launch_bounds__(64,1) ns_kernel(){
    const int b = blockIdx.x;
    const int c = threadIdx.x;
    const long tb = (long)b*SS;
    float ns = 0.f;
    for (int tt=0; tt<SS; tt+=8){
        float gg[8], nn[8], of[8], os[8];
        float4 pw4[8];
        #pragma unroll
        for (int j=0;j<8;j++){
            long tok = tb + tt + j;
            gg[j] = g_gate[tok];
            nn[j] = g_nu[tok*DD + c];
            of[j] = g_outf[tok*DD + c];
            os[j] = g_outs[tok*DD + c];
            pw4[j] = *(const float4*)&g_pw[tok*4];
        }
        #pragma unroll
        for (int j=0;j<8;j++){
            ns = fmaf(gg[j], nn[j] - ns, ns);
            g_outpre[(tb+tt+j)*DD + c] =
                pw4[j].x*of[j] + pw4[j].y*os[j] + pw4[j].z*ns;
        }
    }
}

// ---------------------------------------------------------------------------
// Kernel 9: RMSNorm. warp per row.
// ---------------------------------------------------------------------------
__global__ void __launch_bounds__(256) rms_kernel(const float* __restrict__ norm_w){
    long row = (long)blockIdx.x*8 + (threadIdx.x>>5);
    int lane = threadIdx.x & 31;
    float x0 = g_outpre[row*DD + lane];
    float x1 = g_outpre[row*DD + 32 + lane];
    float ss = x0*x0 + x1*x1;
    #pragma unroll
    for (int d=1; d<32; d<<=1) ss += __shfl_xor_sync(0xffffffffu, ss, d);
    float inv = rsqrtf(ss*(1.0f/64.0f) + 1e-6f);
    g_a[row*DD + lane]      = x0*inv*norm_w[lane];
    g_a[row*DD + 32 + lane] = x1*inv*norm_w[32+lane];
}

// ---------------------------------------------------------------------------
// Kernel 10: out = g_a[8192,64] @ Wo[64,2048]. 64x64 tiles.
// ---------------------------------------------------------------------------
__global__ void __launch_bounds__(256,2) outgemm_kernel(
    const float* __restrict__ Wo, float* __restrict__ out)
{
    __shared__ __align__(16) float AsT[64][68];
    __shared__ __align__(16) float Bs[64][68];
    const int n0   = blockIdx.x*64;
    const int row0 = blockIdx.y*64;
    const int tid  = threadIdx.x;
    #pragma unroll
    for (int l=0;l<4;l++){
        int s = tid + l*256;
        int rr = s>>4, kq = s&15;
        float4 a4 = *(const float4*)&g_a[(long)(row0+rr)*DD + kq*4];
        AsT[kq*4+0][rr]=a4.x; AsT[kq*4+1][rr]=a4.y;
        AsT[kq*4+2][rr]=a4.z; AsT[kq*4+3][rr]=a4.w;
        float4 b4 = *(const float4*)&Wo[(long)rr*NN + n0 + kq*4];
        *(float4*)&Bs[rr][kq*4] = b4;
    }
    __syncthreads();
    const int tr = tid>>4, tc = tid&15;
    float acc[4][4];
    #pragma unroll
    for (int i=0;i<4;i++)
        #pragma unroll
        for (int j=0;j<4;j++) acc[i][j]=0.f;
    #pragma unroll 8
    for (int k=0;k<64;k++){
        float4 a4 = *(const float4*)&AsT[k][tr*4];
        float4 b4 = *(const float4*)&Bs[k][tc*4];
        float am[4]={a4.x,a4.y,a4.z,a4.w}, bn[4]={b4.x,b4.y,b4.z,b4.w};
        #pragma unroll
        for (int i=0;i<4;i++)
            #pragma unroll
            for (int j=0;j<4;j++) acc[i][j]=fmaf(am[i],bn[j],acc[i][j]);
    }
    #pragma unroll
    for (int i=0;i<4;i++){
        *(float4*)&out[(long)(row0+tr*4+i)*NN + n0 + tc*4] =
            make_float4(acc[i][0],acc[i][1],acc[i][2],acc[i][3]);
    }
}

extern "C" void kernel_launch(void* const* d_in, const int* in_sizes, int n_in,
                              void* d_out, int out_size)
{
    const float* x      = (const float*)d_in[0];
    const float* Wk     = (const float*)d_in[1];
    const float* Wv     = (const float*)d_in[2];
    const float* Wq     = (const float*)d_in[3];
    const float* fa     = (const float*)d_in[4];
    const float* sa     = (const float*)d_in[5];
    const float* nm_w1  = (const float*)d_in[6];
    const float* nm_b1  = (const float*)d_in[7];
    const float* nm_w2  = (const float*)d_in[8];
    const float* nm_b2  = (const float*)d_in[9];
    const float* ir_w1  = (const float*)d_in[10];
    const float* ir_b1  = (const float*)d_in[11];
    const float* ir_w2  = (const float*)d_in[12];
    const float* ir_b2  = (const float*)d_in[13];
    const float* pw_w   = (const float*)d_in[14];
    const float* pw_b   = (const float*)d_in[15];
    const float* Wo     = (const float*)d_in[16];
    const float* norm_w = (const float*)d_in[17];
    float* out = (float*)d_out;

    // projmma at launch index 3 for the ncu capture slot.
    irproj_kernel<<<32, 256>>>(x, ir_w1, ir_b1, ir_w2, ir_b2, 0);
    irproj_kernel<<<32, 256>>>(x, ir_w1, ir_b1, ir_w2, ir_b2, 4096);
    pw_kernel<<<128, 256>>>(x, pw_w, pw_b);
    projmma_kernel<<<dim3(64,3), 256>>>(x, Wk, Wv, Wq);
    chunkdots_kernel<<<NCHT, 256>>>();
    prep_kernel<<<dim3(NCHT,2), 64>>>(fa, sa);
    scan_chunk_kernel<<<dim3(16,BB,2), 256>>>(fa, sa);
    nu_kernel<<<1024, 256>>>(nm_w1, nm_b1, nm_w2, nm_b2);
    gate_kernel<<<1024, 256>>>();
    ns_kernel<<<4, 64>>>();
    rms_kernel<<<1024, 256>>>(norm_w);
    outgemm_kernel<<<dim3(32,128), 256>>>(Wo, out);
}

// round 14
// speedup vs baseline: 1.3799x; 1.3799x over previous
#include <cuda_runtime.h>
#include <cuda_bf16.h>
#include <math.h>

#define BB 4
#define SS 2048
#define DD 64
#define NN 2048
#define NTOK (BB*SS)
#define CT 64
#define NCH (SS/CT)
#define NCHT (BB*NCH)

// -------- static device scratch (no allocations allowed) ----------
__device__ float g_k[NTOK*DD];
__device__ float g_q[NTOK*DD];
__device__ float g_v[NTOK*DD];
__device__ float g_h1[NTOK*DD];
__device__ float g_nu[NTOK*DD];
__device__ float g_pw[NTOK*4];
__device__ float g_us[NTOK];
__device__ float g_outf[NTOK*DD];
__device__ float g_outs[NTOK*DD];
__device__ float g_pqf[NTOK*DD];
__device__ float g_pqs[NTOK*DD];
__device__ float g_kk[NCHT*CT*CT];
__device__ float g_qx[NCHT*CT*CT];
__device__ float g_W [2*NCHT*CT*CT];
__device__ float g_A2[2*NCHT*CT*CT];
__device__ float g_gate[NTOK];
__device__ float g_outpre[NTOK*DD];
__device__ float g_a[NTOK*DD];
// bf16 split operands
__device__ __nv_bfloat16 g_xh[NTOK*NN];
__device__ __nv_bfloat16 g_xl[NTOK*NN];
__device__ __nv_bfloat16 g_wth[4*DD*NN];   // [seg][n][k]
__device__ __nv_bfloat16 g_wtl[4*DD*NN];

__device__ __forceinline__ float gelu_exact(float x){
    return 0.5f*x*(1.0f + erff(x*0.70710678118654752f));
}
__device__ __forceinline__ float dot4(float4 a, float4 b){
    return a.x*b.x + a.y*b.y + a.z*b.z + a.w*b.w;
}
__device__ __forceinline__ void mma16816(float* c, const unsigned* a, const unsigned* b){
    asm volatile(
        "mma.sync.aligned.m16n8k16.row.col.f32.bf16.bf16.f32 "
        "{%0,%1,%2,%3}, {%4,%5,%6,%7}, {%8,%9}, {%0,%1,%2,%3};"
        : "+f"(c[0]), "+f"(c[1]), "+f"(c[2]), "+f"(c[3])
        : "r"(a[0]), "r"(a[1]), "r"(a[2]), "r"(a[3]), "r"(b[0]), "r"(b[1]));
}
__device__ __forceinline__ unsigned pack2(__nv_bfloat16 a, __nv_bfloat16 b){
    return ((unsigned)__bfloat16_as_ushort(b) << 16) | (unsigned)__bfloat16_as_ushort(a);
}

// ---------------------------------------------------------------------------
// Kernel 0a: split x into bf16 hi/lo. 16384 blocks x 256 thr, float4/thread.
// ---------------------------------------------------------------------------
__global__ void __launch_bounds__(256) splitx_kernel(const float* __restrict__ x){
    long i4 = (long)blockIdx.x*256 + threadIdx.x;
    float4 v = ((const float4*)x)[i4];
    float f[4] = {v.x, v.y, v.z, v.w};
    __nv_bfloat16 h[4], l[4];
    #pragma unroll
    for (int j=0;j<4;j++){
        h[j] = __float2bfloat16(f[j]);
        l[j] = __float2bfloat16(f[j] - __bfloat162float(h[j]));
    }
    *(uint2*)&g_xh[i4*4] = make_uint2(pack2(h[0],h[1]), pack2(h[2],h[3]));
    *(uint2*)&g_xl[i4*4] = make_uint2(pack2(l[0],l[1]), pack2(l[2],l[3]));
}

// ---------------------------------------------------------------------------
// Kernel 0b: transpose + split the 4 projection weights into [seg][n][k] bf16.
// grid 128 (4 segs x 32 k-tiles), 256 thr, smem transpose.
// ---------------------------------------------------------------------------
__global__ void __launch_bounds__(256) splitw_kernel(
    const float* __restrict__ Wk, const float* __restrict__ Wv,
    const float* __restrict__ Wq, const float* __restrict__ Wi)
{
    __shared__ float T[64][65];
    const int seg = blockIdx.x >> 5;
    const int k0  = (blockIdx.x & 31) * 64;
    const float* __restrict__ W = (seg==0)?Wk:(seg==1)?Wv:(seg==2)?Wq:Wi;
    const int tid = threadIdx.x;
    #pragma unroll
    for (int l=0;l<4;l++){
        int i4 = tid + l*256;
        int kr = i4 >> 4, c4 = (i4 & 15)*4;
        float4 w = *(const float4*)&W[(long)(k0+kr)*DD + c4];
        T[kr][c4+0]=w.x; T[kr][c4+1]=w.y; T[kr][c4+2]=w.z; T[kr][c4+3]=w.w;
    }
    __syncthreads();
    #pragma unroll
    for (int l=0;l<4;l++){
        int idx = tid + l*256;
        int n = idx >> 4, kc = (idx & 15)*4;
        __nv_bfloat16 h[4], lo[4];
        #pragma unroll
        for (int j=0;j<4;j++){
            float f = T[kc+j][n];
            h[j]  = __float2bfloat16(f);
            lo[j] = __float2bfloat16(f - __bfloat162float(h[j]));
        }
        long dst = ((long)seg*DD + n)*NN + k0 + kc;
        *(uint2*)&g_wth[dst] = make_uint2(pack2(h[0],h[1]),  pack2(h[2],h[3]));
        *(uint2*)&g_wtl[dst] = make_uint2(pack2(lo[0],lo[1]), pack2(lo[2],lo[3]));
    }
}

// ---------------------------------------------------------------------------
// Kernel 1: tensor-core projections via split-bf16 mma, pre-split operands.
// grid (64 row-tiles, 4 segments), 256 thr. Tile 128x64, KC=32 (smem 30 KB).
// seg0 k=l2norm, seg1 v, seg2 q=l2norm, seg3 h1 (raw fp32, gate done later).
// ---------------------------------------------------------------------------
#define KC 32
#define ASTR 40
__global__ void __launch_bounds__(256,2) projmma_kernel(){
    __shared__ __align__(16) __nv_bfloat16 Ah[128][ASTR];
    __shared__ __align__(16) __nv_bfloat16 Al[128][ASTR];
    __shared__ __align__(16) __nv_bfloat16 Bh[64][ASTR];
    __shared__ __align__(16) __nv_bfloat16 Bl[64][ASTR];

    const int seg  = blockIdx.y;
    const int row0 = blockIdx.x * 128;
    const int tid  = threadIdx.x;
    const int warp = tid >> 5;
    const int lane = tid & 31;
    const int g = lane >> 2;
    const int t = lane & 3;
    const int wrow = warp * 16;

    float C[8][4];
    #pragma unroll
    for (int n=0;n<8;n++)
        #pragma unroll
        for (int j=0;j<4;j++) C[n][j]=0.f;

    for (int kb = 0; kb < NN; kb += KC){
        // stage x tile: 128 rows x 32 cols = 512 f8 per buffer (pure copies)
        #pragma unroll
        for (int l=0;l<2;l++){
            int idx = tid + l*256;
            int row = idx >> 2, c8 = (idx & 3)*8;
            long src = (long)(row0+row)*NN + kb + c8;
            *(float4*)&Ah[row][c8] = *(const float4*)&g_xh[src];
            *(float4*)&Al[row][c8] = *(const float4*)&g_xl[src];
        }
        // stage W tile: 64 rows x 32 cols = 256 f8 per buffer
        {
            int idx = tid;
            int row = idx >> 2, c8 = (idx & 3)*8;
            long src = ((long)seg*DD + row)*NN + kb + c8;
            *(float4*)&Bh[row][c8] = *(const float4*)&g_wth[src];
            *(float4*)&Bl[row][c8] = *(const float4*)&g_wtl[src];
        }
        __syncthreads();

        #pragma unroll
        for (int ks=0; ks<2; ks++){
            const int k16 = ks*16;
            unsigned ahf[4], alf[4];
            ahf[0] = *(const unsigned*)&Ah[wrow+g  ][k16+t*2];
            ahf[1] = *(const unsigned*)&Ah[wrow+g+8][k16+t*2];
            ahf[2] = *(const unsigned*)&Ah[wrow+g  ][k16+8+t*2];
            ahf[3] = *(const unsigned*)&Ah[wrow+g+8][k16+8+t*2];
            alf[0] = *(const unsigned*)&Al[wrow+g  ][k16+t*2];
            alf[1] = *(const unsigned*)&Al[wrow+g+8][k16+t*2];
            alf[2] = *(const unsigned*)&Al[wrow+g  ][k16+8+t*2];
            alf[3] = *(const unsigned*)&Al[wrow+g+8][k16+8+t*2];
            #pragma unroll
            for (int nt=0; nt<8; nt++){
                const int n = nt*8 + g;
                unsigned bhf[2], blf[2];
                bhf[0] = *(const unsigned*)&Bh[n][k16+t*2];
                bhf[1] = *(const unsigned*)&Bh[n][k16+8+t*2];
                blf[0] = *(const unsigned*)&Bl[n][k16+t*2];
                blf[1] = *(const unsigned*)&Bl[n][k16+8+t*2];
                mma16816(C[nt], ahf, bhf);
                mma16816(C[nt], ahf, blf);
                mma16816(C[nt], alf, bhf);
            }
        }
        __syncthreads();
    }

    float* dst = (seg==0)? g_k : (seg==1)? g_v : (seg==2)? g_q : g_h1;
    const long rlo = row0 + wrow + g;
    const long rhi = rlo + 8;
    if (seg == 1 || seg == 3){
        #pragma unroll
        for (int nt=0; nt<8; nt++){
            *(float2*)&dst[rlo*DD + nt*8 + t*2] = make_float2(C[nt][0], C[nt][1]);
            *(float2*)&dst[rhi*DD + nt*8 + t*2] = make_float2(C[nt][2], C[nt][3]);
        }
    } else {
        float sl = 0.f, sh = 0.f;
        #pragma unroll
        for (int nt=0; nt<8; nt++){
            sl += C[nt][0]*C[nt][0] + C[nt][1]*C[nt][1];
            sh += C[nt][2]*C[nt][2] + C[nt][3]*C[nt][3];
        }
        const unsigned FULL = 0xffffffffu;
        sl += __shfl_xor_sync(FULL, sl, 1); sl += __shfl_xor_sync(FULL, sl, 2);
        sh += __shfl_xor_sync(FULL, sh, 1); sh += __shfl_xor_sync(FULL, sh, 2);
        float il = 1.0f / fmaxf(sqrtf(sl), 1e-12f);
        float ih = 1.0f / fmaxf(sqrtf(sh), 1e-12f);
        #pragma unroll
        for (int nt=0; nt<8; nt++){
            *(float2*)&dst[rlo*DD + nt*8 + t*2] = make_float2(C[nt][0]*il, C[nt][1]*il);
            *(float2*)&dst[rhi*DD + nt*8 + t*2] = make_float2(C[nt][2]*ih, C[nt][3]*ih);
        }
    }
}

// ---------------------------------------------------------------------------
// Kernel 1c: importance gate from h1 (fp32 gelu + dot + threshold). warp/token.
// ---------------------------------------------------------------------------
__global__ void __launch_bounds__(256) irgate_kernel(
    const float* __restrict__ ir_b1, const float* __restrict__ ir_w2,
    const float* __restrict__ ir_b2)
{
    const int warp = threadIdx.x >> 5, lane = threadIdx.x & 31;
    long tok = (long)blockIdx.x*8 + warp;
    float p = gelu_exact(g_h1[tok*DD + lane]      + ir_b1[lane])      * ir_w2[lane]
            + gelu_exact(g_h1[tok*DD + 32 + lane] + ir_b1[32+lane])   * ir_w2[32+lane];
    const unsigned FULL = 0xffffffffu;
    #pragma unroll
    for (int d=1; d<32; d<<=1) p += __shfl_xor_sync(FULL, p, d);
    if (lane==0) g_us[tok] = (p + ir_b2[0]) > 0.f ? 1.f : 0.f;
}

// ---------------------------------------------------------------------------
// Kernel 2: per-chunk Gram matrices.
// ---------------------------------------------------------------------------
__global__ void __launch_bounds__(256) chunkdots_kernel(){
    __shared__ __align__(16) float Ks[CT][68];
    __shared__ __align__(16) float Qs[CT][68];
    const int p = blockIdx.x;
    const long t0 = (long)p*CT;
    const int tid = threadIdx.x;
    const float4* kp = (const float4*)(g_k + t0*DD);
    const float4* qp = (const float4*)(g_q + t0*DD);
    #pragma unroll
    for (int l=0;l<4;l++){
        int f4 = tid + l*256;
        int row = f4 >> 4, col = (f4 & 15)*4;
        *(float4*)&Ks[row][col] = kp[f4];
        *(float4*)&Qs[row][col] = qp[f4];
    }
    __syncthreads();
    #pragma unroll
    for (int m=0;m<16;m++){
        int idx = tid + m*256;
        int i = idx >> 6, j = idx & 63;
        float sk = 0.f, sq = 0.f;
        #pragma unroll
        for (int r4=0;r4<16;r4++){
            float4 kj = *(float4*)&Ks[j][r4*4];
            float4 ki = *(float4*)&Ks[i][r4*4];
            float4 qi = *(float4*)&Qs[i][r4*4];
            sk += dot4(ki,kj);
            sq += dot4(qi,kj);
        }
        g_kk[(long)p*4096 + idx] = sk;
        g_qx[(long)p*4096 + idx] = sq;
    }
}

// ---------------------------------------------------------------------------
// Kernel 3: per chunk-state: build L, invert (I+L) -> W, build A2.
// ---------------------------------------------------------------------------
__global__ void __launch_bounds__(64) prep_kernel(
    const float* __restrict__ fa_p, const float* __restrict__ sa_p)
{
    __shared__ float L[CT][65];
    __shared__ float W[CT][65];
    __shared__ float apow[CT];
    __shared__ float gi[CT];
    const int p = blockIdx.x;
    const int st = blockIdx.y;
    const long t0 = (long)p*CT;
    const int tid = threadIdx.x;
    const float a = st ? *sa_p : *fa_p;
    const float oa = 1.0f - a;
    if (tid == 0){
        float w = 1.f;
        for (int i=0;i<CT;i++){ apow[i] = w; w *= a; }
    }
    gi[tid] = st ? oa*g_us[t0+tid] : oa;
    __syncthreads();
    const long base = (long)p*4096;
    const long obase = ((long)st*NCHT + p)*4096;
    for (int f = tid; f < 4096; f += 64){
        int i = f >> 6, j = f & 63;
        float dec = (j < i) ? apow[i-1-j] : 0.f;
        L[i][j] = dec * gi[i] * g_kk[base+f];
        g_A2[obase+f] = dec * g_qx[base+f];
    }
    __syncthreads();
    {
        const int j = tid;
        for (int i=0;i<CT;i++) W[i][j] = (i==j) ? 1.f : 0.f;
        for (int i=j+1;i<CT;i++){
            float s = 0.f;
            for (int k=j;k<i;k++) s = fmaf(L[i][k], W[k][j], s);
            W[i][j] = -s;
        }
    }
    __syncthreads();
    for (int f = tid; f < 4096; f += 64)
        g_W[obase+f] = W[f>>6][f&63];
}

// ---------------------------------------------------------------------------
// Kernel 4: chunked scan. grid (16, 4, 2), 256 thr.
// ---------------------------------------------------------------------------
__global__ void __launch_bounds__(256,1) scan_chunk_kernel(
    const float* __restrict__ fa_p, const float* __restrict__ sa_p)
{
    __shared__ __align__(16) float Ks[CT][68];
    __shared__ __align__(16) float Ss[CT][68];
    __shared__ __align__(16) float H [4][68];
    __shared__ __align__(16) float T1[4][68];
    __shared__ __align__(16) float Cc[4][68];
    __shared__ __align__(16) float QHs[4][68];
    __shared__ float apow[CT];

    const int cg = blockIdx.x;
    const int b  = blockIdx.y;
    const int st = blockIdx.z;
    const int tid = threadIdx.x;
    const int i = tid >> 2;
    const int c = tid & 3;
    const int colg = cg*4 + c;
    const float a = st ? *sa_p : *fa_p;
    const float oa = 1.0f - a;
    float* __restrict__ outp = st ? g_outs : g_outf;
    float* __restrict__ pqp  = st ? g_pqs  : g_pqf;

    if (tid == 0){
        float w = 1.f;
        for (int t=0;t<CT;t++){ apow[t] = w; w *= a; }
    }
    H[c][i] = 0.f;
    __syncthreads();
    const float a64 = apow[63]*a;

    for (int ch = 0; ch < NCH; ch++){
        const int  pidx = b*NCH + ch;
        const long t0   = (long)pidx*CT;
        const long wbase = ((long)st*NCHT + pidx)*4096;

        {
            const float4* kp = (const float4*)(g_k + t0*DD);
            const float4* qp = (const float4*)(g_q + t0*DD);
            #pragma unroll
            for (int l=0;l<4;l++){
                int f4 = tid + l*256;
                int row = f4 >> 4, col = (f4 & 15)*4;
                *(float4*)&Ks[row][col] = kp[f4];
                *(float4*)&Ss[row][col] = qp[f4];
            }
        }
        __syncthreads();

        {
            float akh = 0.f, aqh = 0.f;
            #pragma unroll
            for (int r4=0;r4<16;r4++){
                float4 h4 = *(float4*)&H [c][r4*4];
                float4 k4 = *(float4*)&Ks[i][r4*4];
                float4 q4 = *(float4*)&Ss[i][r4*4];
                akh += dot4(k4,h4);
                aqh += dot4(q4,h4);
            }
            float giv = st ? oa*g_us[t0+i] : oa;
            float v   = g_v[(t0+i)*DD + colg];
            T1[c][i]  = giv*(v - apow[i]*akh);
            QHs[c][i] = aqh;
        }
        __syncthreads();

        {
            const float4* wp = (const float4*)(g_W + wbase);
            #pragma unroll
            for (int l=0;l<4;l++){
                int f4 = tid + l*256;
                int row = f4 >> 4, col = (f4 & 15)*4;
                *(float4*)&Ss[row][col] = wp[f4];
            }
        }
        __syncthreads();

        {
            float s = 0.f;
            #pragma unroll
            for (int j4=0;j4<16;j4++){
                float4 w4 = *(float4*)&Ss[i][j4*4];
                float4 r4 = *(float4*)&T1[c][j4*4];
                s += dot4(w4,r4);
            }
            Cc[c][i] = s;
        }
        __syncthreads();

        {
            const float4* ap = (const float4*)(g_A2 + wbase);
            #pragma unroll
            for (int l=0;l<4;l++){
                int f4 = tid + l*256;
                int row = f4 >> 4, col = (f4 & 15)*4;
                *(float4*)&Ss[row][col] = ap[f4];
            }
        }
        __syncthreads();

        {
            float s = 0.f;
            #pragma unroll
            for (int j4=0;j4<16;j4++){
                float4 a4 = *(float4*)&Ss[i][j4*4];
                float4 c4 = *(float4*)&Cc[c][j4*4];
                s += dot4(a4,c4);
            }
            float ci = Cc[c][i];
            float pq = fmaf(apow[i], QHs[c][i], s);
            float qk = g_qx[(long)pidx*4096 + i*65];
            float o  = fmaf(qk, ci, a*pq);
            pqp [(t0+i)*DD + colg] = pq;
            outp[(t0+i)*DD + colg] = o;
            T1[c][i] = apow[63-i]*ci;
        }
        __syncthreads();

        {
            float h = a64*H[c][i];
            #pragma unroll
            for (int j=0;j<CT;j++)
                h = fmaf(Ks[j][i], T1[c][j], h);
            H[c][i] = h;
        }
        __syncthreads();
    }
}

// ---------------------------------------------------------------------------
// Kernel 5: pw = softmax(x @ pw_w + pw_b). warp per token.
// ---------------------------------------------------------------------------
__global__ void __launch_bounds__(256) pw_kernel(
    const float* __restrict__ x, const float* __restrict__ pw_w,
    const float* __restrict__ pw_b)
{
    __shared__ __align__(16) float pwT[3][2048];
    const int tid = threadIdx.x;
    for (int idx = tid; idx < 3*2048; idx += 256){
        int i = idx/3, cc = idx - i*3;
        pwT[cc][i] = pw_w[idx];
    }
    __syncthreads();
    const int warp = tid>>5, lane = tid&31;
    const float b0 = pw_b[0], b1 = pw_b[1], b2 = pw_b[2];
    const unsigned FULL = 0xffffffffu;
    for (int it8 = 0; it8 < 8; it8++){
        long tok = (long)blockIdx.x*64 + warp*8 + it8;
        const float* xr = x + tok*NN;
        float a0=0.f,a1=0.f,a2=0.f;
        #pragma unroll
        for (int it=0; it<16; it++){
            int off = it*128 + lane*4;
            float4 xv = *(const float4*)&xr[off];
            float4 w0 = *(const float4*)&pwT[0][off];
            float4 w1 = *(const float4*)&pwT[1][off];
            float4 w2 = *(const float4*)&pwT[2][off];
            a0 += dot4(xv,w0);
            a1 += dot4(xv,w1);
            a2 += dot4(xv,w2);
        }
        #pragma unroll
        for (int d=1; d<32; d<<=1){
            a0 += __shfl_xor_sync(FULL, a0, d);
            a1 += __shfl_xor_sync(FULL, a1, d);
            a2 += __shfl_xor_sync(FULL, a2, d);
        }
        if (lane==0){
            float l0=a0+b0, l1=a1+b1, l2=a2+b2;
            float m = fmaxf(l0, fmaxf(l1,l2));
            float e0=expf(l0-m), e1=expf(l1-m), e2=expf(l2-m);
            float inv = 1.0f/(e0+e1+e2);
            g_pw[tok*4+0]=e0*inv; g_pw[tok*4+1]=e1*inv;
            g_pw[tok*4+2]=e2*inv; g_pw[tok*4+3]=0.f;
        }
    }
}

// ---------------------------------------------------------------------------
// Kernel 6: nu = gelu(v @ nm_w1 + b1) @ nm_w2 + b2. warp per token.
// ---------------------------------------------------------------------------
__global__ void __launch_bounds__(256) nu_kernel(
    const float* __restrict__ nm_w1, const float* __restrict__ nm_b1,
    const float* __restrict__ nm_w2, const float* __restrict__ nm_b2)
{
    __shared__ float W1s[64*128];
    __shared__ float hs[8][128];
    __shared__ float vs[8][64];
    const int tid = threadIdx.x;
    for (int i = tid; i < 64*128; i += 256) W1s[i] = nm_w1[i];
    long tok0 = (long)blockIdx.x*8;
    for (int i = tid; i < 8*64; i += 256){
        int t = i>>6, r = i&63;
        vs[t][r] = g_v[(tok0+t)*DD + r];
    }
    __syncthreads();
    const int warp = tid>>5, lane = tid&31;
    #pragma unroll
    for (int ii=0;ii<4;ii++){
        int i = lane + ii*32;
        float a = nm_b1[i];
        #pragma unroll 8
        for (int r=0;r<64;r++) a = fmaf(vs[warp][r], W1s[r*128+i], a);
        hs[warp][i] = gelu_exact(a);
    }
    __syncwarp();
    #pragma unroll
    for (int jj=0;jj<2;jj++){
        int j = lane + jj*32;
        float a = nm_b2[j];
        #pragma unroll 8
        for (int i=0;i<128;i++) a = fmaf(hs[warp][i], __ldg(&nm_w2[i*64+j]), a);
        g_nu[(tok0+warp)*DD + j] = a;
    }
}

// ---------------------------------------------------------------------------
// Kernel 7: gate from reconstructed error. warp per token.
// ---------------------------------------------------------------------------
__global__ void __launch_bounds__(256) gate_kernel(){
    const int tid = threadIdx.x;
    const int warp = tid>>5, lane = tid&31;
    long tok = (long)blockIdx.x*8 + warp;
    float s = 0.f;
    #pragma unroll
    for (int h=0; h<2; h++){
        int c = lane + h*32;
        float v  = g_v[tok*DD + c];
        float pf = g_pqf[tok*DD + c];
        float ps = g_pqs[tok*DD + c];
        float e = v - 0.5f*(pf + ps);
        s += e*e;
    }
    const unsigned FULL = 0xffffffffu;
    #pragma unroll
    for (int d=1; d<32; d<<=1) s += __shfl_xor_sync(FULL,s,d);
    if (lane==0){
        g_gate[tok] = (s > 0.84729871f) ? 0.1f : 0.0f;
    }
}

// ---------------------------------------------------------------------------
// Kernel 8: ns scan + pw combine, unroll-8 with batched prefetch.
// ---------------------------------------------------------------------------
__global__ void __launch_bounds__(64,1) ns_kernel(){
    const int b = blockIdx.x;
    const int c = threadIdx.x;
    const long tb = (long)b*SS;
    float ns = 0.f;
    for (int tt=0; tt<SS; tt+=8){
        float gg[8], nn[8], of[8], os[8];
        float4 pw4[8];
        #pragma unroll
        for (int j=0;j<8;j++){
            long tok = tb + tt + j;
            gg[j] = g_gate[tok];
            nn[j] = g_nu[tok*DD + c];
            of[j] = g_outf[tok*DD + c];
            os[j] = g_outs[tok*DD + c];
            pw4[j] = *(const float4*)&g_pw[tok*4];
        }
        #pragma unroll
        for (int j=0;j<8;j++){
            ns = fmaf(gg[j], nn[j] - ns, ns);
            g_outpre[(tb+tt+j)*DD + c] =
                pw4[j].x*of[j] + pw4[j].y*os[j] + pw4[j].z*ns;
        }
    }
}

// ---------------------------------------------------------------------------
// Kernel 9: RMSNorm. warp per row.
// ---------------------------------------------------------------------------
__global__ void __launch_bounds__(256) rms_kernel(const float* __restrict__ norm_w){
    long row = (long)blockIdx.x*8 + (threadIdx.x>>5);
    int lane = threadIdx.x & 31;
    float x0 = g_outpre[row*DD + lane];
    float x1 = g_outpre[row*DD + 32 + lane];
    float ss = x0*x0 + x1*x1;
    #pragma unroll
    for (int d=1; d<32; d<<=1) ss += __shfl_xor_sync(0xffffffffu, ss, d);
    float inv = rsqrtf(ss*(1.0f/64.0f) + 1e-6f);
    g_a[row*DD + lane]      = x0*inv*norm_w[lane];
    g_a[row*DD + 32 + lane] = x1*inv*norm_w[32+lane];
}

// ---------------------------------------------------------------------------
// Kernel 10: out = g_a[8192,64] @ Wo[64,2048]. 64x64 tiles.
// ---------------------------------------------------------------------------
__global__ void __launch_bounds__(256,2) outgemm_kernel(
    const float* __restrict__ Wo, float* __restrict__ out)
{
    __shared__ __align__(16) float AsT[64][68];
    __shared__ __align__(16) float Bs[64][68];
    const int n0   = blockIdx.x*64;
    const int row0 = blockIdx.y*64;
    const int tid  = threadIdx.x;
    #pragma unroll
    for (int l=0;l<4;l++){
        int s = tid + l*256;
        int rr = s>>4, kq = s&15;
        float4 a4 = *(const float4*)&g_a[(long)(row0+rr)*DD + kq*4];
        AsT[kq*4+0][rr]=a4.x; AsT[kq*4+1][rr]=a4.y;
        AsT[kq*4+2][rr]=a4.z; AsT[kq*4+3][rr]=a4.w;
        float4 b4 = *(const float4*)&Wo[(long)rr*NN + n0 + kq*4];
        *(float4*)&Bs[rr][kq*4] = b4;
    }
    __syncthreads();
    const int tr = tid>>4, tc = tid&15;
    float acc[4][4];
    #pragma unroll
    for (int i=0;i<4;i++)
        #pragma unroll
        for (int j=0;j<4;j++) acc[i][j]=0.f;
    #pragma unroll 8
    for (int k=0;k<64;k++){
        float4 a4 = *(const float4*)&AsT[k][tr*4];
        float4 b4 = *(const float4*)&Bs[k][tc*4];
        float am[4]={a4.x,a4.y,a4.z,a4.w}, bn[4]={b4.x,b4.y,b4.z,b4.w};
        #pragma unroll
        for (int i=0;i<4;i++)
            #pragma unroll
            for (int j=0;j<4;j++) acc[i][j]=fmaf(am[i],bn[j],acc[i][j]);
    }
    #pragma unroll
    for (int i=0;i<4;i++){
        *(float4*)&out[(long)(row0+tr*4+i)*NN + n0 + tc*4] =
            make_float4(acc[i][0],acc[i][1],acc[i][2],acc[i][3]);
    }
}

extern "C" void kernel_launch(void* const* d_in, const int* in_sizes, int n_in,
                              void* d_out, int out_size)
{
    const float* x      = (const float*)d_in[0];
    const float* Wk     = (const float*)d_in[1];
    const float* Wv     = (const float*)d_in[2];
    const float* Wq     = (const float*)d_in[3];
    const float* fa     = (const float*)d_in[4];
    const float* sa     = (const float*)d_in[5];
    const float* nm_w1  = (const float*)d_in[6];
    const float* nm_b1  = (const float*)d_in[7];
    const float* nm_w2  = (const float*)d_in[8];
    const float* nm_b2  = (const float*)d_in[9];
    const float* ir_w1  = (const float*)d_in[10];
    const float* ir_b1  = (const float*)d_in[11];
    const float* ir_w2  = (const float*)d_in[12];
    const float* ir_b2  = (const float*)d_in[13];
    const float* pw_w   = (const float*)d_in[14];
    const float* pw_b   = (const float*)d_in[15];
    const float* Wo     = (const float*)d_in[16];
    const float* norm_w = (const float*)d_in[17];
    float* out = (float*)d_out;

    // projmma at launch index 3 for the ncu capture slot.
    splitx_kernel<<<16384, 256>>>(x);
    splitw_kernel<<<128, 256>>>(Wk, Wv, Wq, ir_w1);
    pw_kernel<<<128, 256>>>(x, pw_w, pw_b);
    projmma_kernel<<<dim3(64,4), 256>>>();
    irgate_kernel<<<1024, 256>>>(ir_b1, ir_w2, ir_b2);
    chunkdots_kernel<<<NCHT, 256>>>();
    prep_kernel<<<dim3(NCHT,2), 64>>>(fa, sa);
    scan_chunk_kernel<<<dim3(16,BB,2), 256>>>(fa, sa);
    nu_kernel<<<1024, 256>>>(nm_w1, nm_b1, nm_w2, nm_b2);
    gate_kernel<<<1024, 256>>>();
    ns_kernel<<<4, 64>>>();
    rms_kernel<<<1024, 256>>>(norm_w);
    outgemm_kernel<<<dim3(32,128), 256>>>(Wo, out);
}

// round 15
// speedup vs baseline: 1.3857x; 1.0041x over previous
#include <cuda_runtime.h>
#include <cuda_bf16.h>
#include <math.h>

#define BB 4
#define SS 2048
#define DD 64
#define NN 2048
#define NTOK (BB*SS)
#define CT 64
#define NCH (SS/CT)
#define NCHT (BB*NCH)

// -------- static device scratch (no allocations allowed) ----------
__device__ float g_k[NTOK*DD];
__device__ float g_q[NTOK*DD];
__device__ float g_v[NTOK*DD];
__device__ float g_h1[NTOK*DD];
__device__ float g_nu[NTOK*DD];
__device__ float g_pw[NTOK*4];
__device__ float g_us[NTOK];
__device__ float g_outf[NTOK*DD];
__device__ float g_outs[NTOK*DD];
__device__ float g_pqf[NTOK*DD];
__device__ float g_pqs[NTOK*DD];
__device__ float g_kk[NCHT*CT*CT];
__device__ float g_qx[NCHT*CT*CT];
__device__ float g_W [2*NCHT*CT*CT];
__device__ float g_A2[2*NCHT*CT*CT];
__device__ float g_gate[NTOK];
__device__ float g_outpre[NTOK*DD];
__device__ float g_a[NTOK*DD];
// bf16 split operands
__device__ __nv_bfloat16 g_xh[NTOK*NN];
__device__ __nv_bfloat16 g_xl[NTOK*NN];
__device__ __nv_bfloat16 g_wth[4*DD*NN];   // [seg][n][k]
__device__ __nv_bfloat16 g_wtl[4*DD*NN];

__device__ __forceinline__ float gelu_exact(float x){
    return 0.5f*x*(1.0f + erff(x*0.70710678118654752f));
}
__device__ __forceinline__ float dot4(float4 a, float4 b){
    return a.x*b.x + a.y*b.y + a.z*b.z + a.w*b.w;
}
__device__ __forceinline__ void mma16816(float* c, const unsigned* a, const unsigned* b){
    asm volatile(
        "mma.sync.aligned.m16n8k16.row.col.f32.bf16.bf16.f32 "
        "{%0,%1,%2,%3}, {%4,%5,%6,%7}, {%8,%9}, {%0,%1,%2,%3};"
        : "+f"(c[0]), "+f"(c[1]), "+f"(c[2]), "+f"(c[3])
        : "r"(a[0]), "r"(a[1]), "r"(a[2]), "r"(a[3]), "r"(b[0]), "r"(b[1]));
}
__device__ __forceinline__ unsigned pack2(__nv_bfloat16 a, __nv_bfloat16 b){
    return ((unsigned)__bfloat16_as_ushort(b) << 16) | (unsigned)__bfloat16_as_ushort(a);
}

// ---------------------------------------------------------------------------
// Kernel 0a: split x into bf16 hi/lo. 16384 blocks x 256 thr, float4/thread.
// ---------------------------------------------------------------------------
__global__ void __launch_bounds__(256) splitx_kernel(const float* __restrict__ x){
    long i4 = (long)blockIdx.x*256 + threadIdx.x;
    float4 v = ((const float4*)x)[i4];
    float f[4] = {v.x, v.y, v.z, v.w};
    __nv_bfloat16 h[4], l[4];
    #pragma unroll
    for (int j=0;j<4;j++){
        h[j] = __float2bfloat16(f[j]);
        l[j] = __float2bfloat16(f[j] - __bfloat162float(h[j]));
    }
    *(uint2*)&g_xh[i4*4] = make_uint2(pack2(h[0],h[1]), pack2(h[2],h[3]));
    *(uint2*)&g_xl[i4*4] = make_uint2(pack2(l[0],l[1]), pack2(l[2],l[3]));
}

// ---------------------------------------------------------------------------
// Kernel 0b: transpose + split the 4 projection weights into [seg][n][k] bf16.
// grid 128 (4 segs x 32 k-tiles), 256 thr, smem transpose.
// ---------------------------------------------------------------------------
__global__ void __launch_bounds__(256) splitw_kernel(
    const float* __restrict__ Wk, const float* __restrict__ Wv,
    const float* __restrict__ Wq, const float* __restrict__ Wi)
{
    __shared__ float T[64][65];
    const int seg = blockIdx.x >> 5;
    const int k0  = (blockIdx.x & 31) * 64;
    const float* __restrict__ W = (seg==0)?Wk:(seg==1)?Wv:(seg==2)?Wq:Wi;
    const int tid = threadIdx.x;
    #pragma unroll
    for (int l=0;l<4;l++){
        int i4 = tid + l*256;
        int kr = i4 >> 4, c4 = (i4 & 15)*4;
        float4 w = *(const float4*)&W[(long)(k0+kr)*DD + c4];
        T[kr][c4+0]=w.x; T[kr][c4+1]=w.y; T[kr][c4+2]=w.z; T[kr][c4+3]=w.w;
    }
    __syncthreads();
    #pragma unroll
    for (int l=0;l<4;l++){
        int idx = tid + l*256;
        int n = idx >> 4, kc = (idx & 15)*4;
        __nv_bfloat16 h[4], lo[4];
        #pragma unroll
        for (int j=0;j<4;j++){
            float f = T[kc+j][n];
            h[j]  = __float2bfloat16(f);
            lo[j] = __float2bfloat16(f - __bfloat162float(h[j]));
        }
        long dst = ((long)seg*DD + n)*NN + k0 + kc;
        *(uint2*)&g_wth[dst] = make_uint2(pack2(h[0],h[1]),  pack2(h[2],h[3]));
        *(uint2*)&g_wtl[dst] = make_uint2(pack2(lo[0],lo[1]), pack2(lo[2],lo[3]));
    }
}

// ---------------------------------------------------------------------------
// Kernel 1: tensor-core projections via split-bf16 mma, pre-split operands.
// grid (64 row-tiles, 4 segments), 256 thr. Tile 128x64, KC=32 (smem 30 KB).
// seg0 k=l2norm, seg1 v, seg2 q=l2norm, seg3 h1 (raw fp32, gate done later).
// ---------------------------------------------------------------------------
#define KC 32
#define ASTR 40
__global__ void __launch_bounds__(256,2) projmma_kernel(){
    __shared__ __align__(16) __nv_bfloat16 Ah[128][ASTR];
    __shared__ __align__(16) __nv_bfloat16 Al[128][ASTR];
    __shared__ __align__(16) __nv_bfloat16 Bh[64][ASTR];
    __shared__ __align__(16) __nv_bfloat16 Bl[64][ASTR];

    const int seg  = blockIdx.y;
    const int row0 = blockIdx.x * 128;
    const int tid  = threadIdx.x;
    const int warp = tid >> 5;
    const int lane = tid & 31;
    const int g = lane >> 2;
    const int t = lane & 3;
    const int wrow = warp * 16;

    float C[8][4];
    #pragma unroll
    for (int n=0;n<8;n++)
        #pragma unroll
        for (int j=0;j<4;j++) C[n][j]=0.f;

    for (int kb = 0; kb < NN; kb += KC){
        // stage x tile: 128 rows x 32 cols = 512 f8 per buffer (pure copies)
        #pragma unroll
        for (int l=0;l<2;l++){
            int idx = tid + l*256;
            int row = idx >> 2, c8 = (idx & 3)*8;
            long src = (long)(row0+row)*NN + kb + c8;
            *(float4*)&Ah[row][c8] = *(const float4*)&g_xh[src];
            *(float4*)&Al[row][c8] = *(const float4*)&g_xl[src];
        }
        // stage W tile: 64 rows x 32 cols = 256 f8 per buffer
        {
            int idx = tid;
            int row = idx >> 2, c8 = (idx & 3)*8;
            long src = ((long)seg*DD + row)*NN + kb + c8;
            *(float4*)&Bh[row][c8] = *(const float4*)&g_wth[src];
            *(float4*)&Bl[row][c8] = *(const float4*)&g_wtl[src];
        }
        __syncthreads();

        #pragma unroll
        for (int ks=0; ks<2; ks++){
            const int k16 = ks*16;
            unsigned ahf[4], alf[4];
            ahf[0] = *(const unsigned*)&Ah[wrow+g  ][k16+t*2];
            ahf[1] = *(const unsigned*)&Ah[wrow+g+8][k16+t*2];
            ahf[2] = *(const unsigned*)&Ah[wrow+g  ][k16+8+t*2];
            ahf[3] = *(const unsigned*)&Ah[wrow+g+8][k16+8+t*2];
            alf[0] = *(const unsigned*)&Al[wrow+g  ][k16+t*2];
            alf[1] = *(const unsigned*)&Al[wrow+g+8][k16+t*2];
            alf[2] = *(const unsigned*)&Al[wrow+g  ][k16+8+t*2];
            alf[3] = *(const unsigned*)&Al[wrow+g+8][k16+8+t*2];
            #pragma unroll
            for (int nt=0; nt<8; nt++){
                const int n = nt*8 + g;
                unsigned bhf[2], blf[2];
                bhf[0] = *(const unsigned*)&Bh[n][k16+t*2];
                bhf[1] = *(const unsigned*)&Bh[n][k16+8+t*2];
                blf[0] = *(const unsigned*)&Bl[n][k16+t*2];
                blf[1] = *(const unsigned*)&Bl[n][k16+8+t*2];
                mma16816(C[nt], ahf, bhf);
                mma16816(C[nt], ahf, blf);
                mma16816(C[nt], alf, bhf);
            }
        }
        __syncthreads();
    }

    float* dst = (seg==0)? g_k : (seg==1)? g_v : (seg==2)? g_q : g_h1;
    const long rlo = row0 + wrow + g;
    const long rhi = rlo + 8;
    if (seg == 1 || seg == 3){
        #pragma unroll
        for (int nt=0; nt<8; nt++){
            *(float2*)&dst[rlo*DD + nt*8 + t*2] = make_float2(C[nt][0], C[nt][1]);
            *(float2*)&dst[rhi*DD + nt*8 + t*2] = make_float2(C[nt][2], C[nt][3]);
        }
    } else {
        float sl = 0.f, sh = 0.f;
        #pragma unroll
        for (int nt=0; nt<8; nt++){
            sl += C[nt][0]*C[nt][0] + C[nt][1]*C[nt][1];
            sh += C[nt][2]*C[nt][2] + C[nt][3]*C[nt][3];
        }
        const unsigned FULL = 0xffffffffu;
        sl += __shfl_xor_sync(FULL, sl, 1); sl += __shfl_xor_sync(FULL, sl, 2);
        sh += __shfl_xor_sync(FULL, sh, 1); sh += __shfl_xor_sync(FULL, sh, 2);
        float il = 1.0f / fmaxf(sqrtf(sl), 1e-12f);
        float ih = 1.0f / fmaxf(sqrtf(sh), 1e-12f);
        #pragma unroll
        for (int nt=0; nt<8; nt++){
            *(float2*)&dst[rlo*DD + nt*8 + t*2] = make_float2(C[nt][0]*il, C[nt][1]*il);
            *(float2*)&dst[rhi*DD + nt*8 + t*2] = make_float2(C[nt][2]*ih, C[nt][3]*ih);
        }
    }
}

// ---------------------------------------------------------------------------
// Kernel 1c: importance gate from h1 (fp32 gelu + dot + threshold). warp/token.
// ---------------------------------------------------------------------------
__global__ void __launch_bounds__(256) irgate_kernel(
    const float* __restrict__ ir_b1, const float* __restrict__ ir_w2,
    const float* __restrict__ ir_b2)
{
    const int warp = threadIdx.x >> 5, lane = threadIdx.x & 31;
    long tok = (long)blockIdx.x*8 + warp;
    float p = gelu_exact(g_h1[tok*DD + lane]      + ir_b1[lane])      * ir_w2[lane]
            + gelu_exact(g_h1[tok*DD + 32 + lane] + ir_b1[32+lane])   * ir_w2[32+lane];
    const unsigned FULL = 0xffffffffu;
    #pragma unroll
    for (int d=1; d<32; d<<=1) p += __shfl_xor_sync(FULL, p, d);
    if (lane==0) g_us[tok] = (p + ir_b2[0]) > 0.f ? 1.f : 0.f;
}

// ---------------------------------------------------------------------------
// Kernel 2: per-chunk Gram matrices.
// ---------------------------------------------------------------------------
__global__ void __launch_bounds__(256) chunkdots_kernel(){
    __shared__ __align__(16) float Ks[CT][68];
    __shared__ __align__(16) float Qs[CT][68];
    const int p = blockIdx.x;
    const long t0 = (long)p*CT;
    const int tid = threadIdx.x;
    const float4* kp = (const float4*)(g_k + t0*DD);
    const float4* qp = (const float4*)(g_q + t0*DD);
    #pragma unroll
    for (int l=0;l<4;l++){
        int f4 = tid + l*256;
        int row = f4 >> 4, col = (f4 & 15)*4;
        *(float4*)&Ks[row][col] = kp[f4];
        *(float4*)&Qs[row][col] = qp[f4];
    }
    __syncthreads();
    #pragma unroll
    for (int m=0;m<16;m++){
        int idx = tid + m*256;
        int i = idx >> 6, j = idx & 63;
        float sk = 0.f, sq = 0.f;
        #pragma unroll
        for (int r4=0;r4<16;r4++){
            float4 kj = *(float4*)&Ks[j][r4*4];
            float4 ki = *(float4*)&Ks[i][r4*4];
            float4 qi = *(float4*)&Qs[i][r4*4];
            sk += dot4(ki,kj);
            sq += dot4(qi,kj);
        }
        g_kk[(long)p*4096 + idx] = sk;
        g_qx[(long)p*4096 + idx] = sq;
    }
}

// ---------------------------------------------------------------------------
// Kernel 3: per chunk-state: build L, invert (I+L) -> W, build A2.
// ---------------------------------------------------------------------------
__global__ void __launch_bounds__(64) prep_kernel(
    const float* __restrict__ fa_p, const float* __restrict__ sa_p)
{
    __shared__ float L[CT][65];
    __shared__ float W[CT][65];
    __shared__ float apow[CT];
    __shared__ float gi[CT];
    const int p = blockIdx.x;
    const int st = blockIdx.y;
    const long t0 = (long)p*CT;
    const int tid = threadIdx.x;
    const float a = st ? *sa_p : *fa_p;
    const float oa = 1.0f - a;
    if (tid == 0){
        float w = 1.f;
        for (int i=0;i<CT;i++){ apow[i] = w; w *= a; }
    }
    gi[tid] = st ? oa*g_us[t0+tid] : oa;
    __syncthreads();
    const long base = (long)p*4096;
    const long obase = ((long)st*NCHT + p)*4096;
    for (int f = tid; f < 4096; f += 64){
        int i = f >> 6, j = f & 63;
        float dec = (j < i) ? apow[i-1-j] : 0.f;
        L[i][j] = dec * gi[i] * g_kk[base+f];
        g_A2[obase+f] = dec * g_qx[base+f];
    }
    __syncthreads();
    {
        const int j = tid;
        for (int i=0;i<CT;i++) W[i][j] = (i==j) ? 1.f : 0.f;
        for (int i=j+1;i<CT;i++){
            float s = 0.f;
            for (int k=j;k<i;k++) s = fmaf(L[i][k], W[k][j], s);
            W[i][j] = -s;
        }
    }
    __syncthreads();
    for (int f = tid; f < 4096; f += 64)
        g_W[obase+f] = W[f>>6][f&63];
}

// ---------------------------------------------------------------------------
// Kernel 4: chunked scan. grid (16, 4, 2), 256 thr.
// ---------------------------------------------------------------------------
__global__ void __launch_bounds__(256,1) scan_chunk_kernel(
    const float* __restrict__ fa_p, const float* __restrict__ sa_p)
{
    __shared__ __align__(16) float Ks[CT][68];
    __shared__ __align__(16) float Ss[CT][68];
    __shared__ __align__(16) float H [4][68];
    __shared__ __align__(16) float T1[4][68];
    __shared__ __align__(16) float Cc[4][68];
    __shared__ __align__(16) float QHs[4][68];
    __shared__ float apow[CT];

    const int cg = blockIdx.x;
    const int b  = blockIdx.y;
    const int st = blockIdx.z;
    const int tid = threadIdx.x;
    const int i = tid >> 2;
    const int c = tid & 3;
    const int colg = cg*4 + c;
    const float a = st ? *sa_p : *fa_p;
    const float oa = 1.0f - a;
    float* __restrict__ outp = st ? g_outs : g_outf;
    float* __restrict__ pqp  = st ? g_pqs  : g_pqf;

    if (tid == 0){
        float w = 1.f;
        for (int t=0;t<CT;t++){ apow[t] = w; w *= a; }
    }
    H[c][i] = 0.f;
    __syncthreads();
    const float a64 = apow[63]*a;

    for (int ch = 0; ch < NCH; ch++){
        const int  pidx = b*NCH + ch;
        const long t0   = (long)pidx*CT;
        const long wbase = ((long)st*NCHT + pidx)*4096;

        {
            const float4* kp = (const float4*)(g_k + t0*DD);
            const float4* qp = (const float4*)(g_q + t0*DD);
            #pragma unroll
            for (int l=0;l<4;l++){
                int f4 = tid + l*256;
                int row = f4 >> 4, col = (f4 & 15)*4;
                *(float4*)&Ks[row][col] = kp[f4];
                *(float4*)&Ss[row][col] = qp[f4];
            }
        }
        __syncthreads();

        {
            float akh = 0.f, aqh = 0.f;
            #pragma unroll
            for (int r4=0;r4<16;r4++){
                float4 h4 = *(float4*)&H [c][r4*4];
                float4 k4 = *(float4*)&Ks[i][r4*4];
                float4 q4 = *(float4*)&Ss[i][r4*4];
                akh += dot4(k4,h4);
                aqh += dot4(q4,h4);
            }
            float giv = st ? oa*g_us[t0+i] : oa;
            float v   = g_v[(t0+i)*DD + colg];
            T1[c][i]  = giv*(v - apow[i]*akh);
            QHs[c][i] = aqh;
        }
        __syncthreads();

        {
            const float4* wp = (const float4*)(g_W + wbase);
            #pragma unroll
            for (int l=0;l<4;l++){
                int f4 = tid + l*256;
                int row = f4 >> 4, col = (f4 & 15)*4;
                *(float4*)&Ss[row][col] = wp[f4];
            }
        }
        __syncthreads();

        {
            float s = 0.f;
            #pragma unroll
            for (int j4=0;j4<16;j4++){
                float4 w4 = *(float4*)&Ss[i][j4*4];
                float4 r4 = *(float4*)&T1[c][j4*4];
                s += dot4(w4,r4);
            }
            Cc[c][i] = s;
        }
        __syncthreads();

        {
            const float4* ap = (const float4*)(g_A2 + wbase);
            #pragma unroll
            for (int l=0;l<4;l++){
                int f4 = tid + l*256;
                int row = f4 >> 4, col = (f4 & 15)*4;
                *(float4*)&Ss[row][col] = ap[f4];
            }
        }
        __syncthreads();

        {
            float s = 0.f;
            #pragma unroll
            for (int j4=0;j4<16;j4++){
                float4 a4 = *(float4*)&Ss[i][j4*4];
                float4 c4 = *(float4*)&Cc[c][j4*4];
                s += dot4(a4,c4);
            }
            float ci = Cc[c][i];
            float pq = fmaf(apow[i], QHs[c][i], s);
            float qk = g_qx[(long)pidx*4096 + i*65];
            float o  = fmaf(qk, ci, a*pq);
            pqp [(t0+i)*DD + colg] = pq;
            outp[(t0+i)*DD + colg] = o;
            T1[c][i] = apow[63-i]*ci;
        }
        __syncthreads();

        {
            float h = a64*H[c][i];
            #pragma unroll
            for (int j=0;j<CT;j++)
                h = fmaf(Ks[j][i], T1[c][j], h);
            H[c][i] = h;
        }
        __syncthreads();
    }
}

// ---------------------------------------------------------------------------
// Kernel 5: pw = softmax(x @ pw_w + pw_b). warp per token.
// ---------------------------------------------------------------------------
__global__ void __launch_bounds__(256) pw_kernel(
    const float* __restrict__ x, const float* __restrict__ pw_w,
    const float* __restrict__ pw_b)
{
    __shared__ __align__(16) float pwT[3][2048];
    const int tid = threadIdx.x;
    for (int idx = tid; idx < 3*2048; idx += 256){
        int i = idx/3, cc = idx - i*3;
        pwT[cc][i] = pw_w[idx];
    }
    __syncthreads();
    const int warp = tid>>5, lane = tid&31;
    const float b0 = pw_b[0], b1 = pw_b[1], b2 = pw_b[2];
    const unsigned FULL = 0xffffffffu;
    for (int it8 = 0; it8 < 8; it8++){
        long tok = (long)blockIdx.x*64 + warp*8 + it8;
        const float* xr = x + tok*NN;
        float a0=0.f,a1=0.f,a2=0.f;
        #pragma unroll
        for (int it=0; it<16; it++){
            int off = it*128 + lane*4;
            float4 xv = *(const float4*)&xr[off];
            float4 w0 = *(const float4*)&pwT[0][off];
            float4 w1 = *(const float4*)&pwT[1][off];
            float4 w2 = *(const float4*)&pwT[2][off];
            a0 += dot4(xv,w0);
            a1 += dot4(xv,w1);
            a2 += dot4(xv,w2);
        }
        #pragma unroll
        for (int d=1; d<32; d<<=1){
            a0 += __shfl_xor_sync(FULL, a0, d);
            a1 += __shfl_xor_sync(FULL, a1, d);
            a2 += __shfl_xor_sync(FULL, a2, d);
        }
        if (lane==0){
            float l0=a0+b0, l1=a1+b1, l2=a2+b2;
            float m = fmaxf(l0, fmaxf(l1,l2));
            float e0=expf(l0-m), e1=expf(l1-m), e2=expf(l2-m);
            float inv = 1.0f/(e0+e1+e2);
            g_pw[tok*4+0]=e0*inv; g_pw[tok*4+1]=e1*inv;
            g_pw[tok*4+2]=e2*inv; g_pw[tok*4+3]=0.f;
        }
    }
}

// ---------------------------------------------------------------------------
// Kernel 6: nu = gelu(v @ nm_w1 + b1) @ nm_w2 + b2. warp per token.
// ---------------------------------------------------------------------------
__global__ void __launch_bounds__(256) nu_kernel(
    const float* __restrict__ nm_w1, const float* __restrict__ nm_b1,
    const float* __restrict__ nm_w2, const float* __restrict__ nm_b2)
{
    __shared__ float W1s[64*128];
    __shared__ float hs[8][128];
    __shared__ float vs[8][64];
    const int tid = threadIdx.x;
    for (int i = tid; i < 64*128; i += 256) W1s[i] = nm_w1[i];
    long tok0 = (long)blockIdx.x*8;
    for (int i = tid; i < 8*64; i += 256){
        int t = i>>6, r = i&63;
        vs[t][r] = g_v[(tok0+t)*DD + r];
    }
    __syncthreads();
    const int warp = tid>>5, lane = tid&31;
    #pragma unroll
    for (int ii=0;ii<4;ii++){
        int i = lane + ii*32;
        float a = nm_b1[i];
        #pragma unroll 8
        for (int r=0;r<64;r++) a = fmaf(vs[warp][r], W1s[r*128+i], a);
        hs[warp][i] = gelu_exact(a);
    }
    __syncwarp();
    #pragma unroll
    for (int jj=0;jj<2;jj++){
        int j = lane + jj*32;
        float a = nm_b2[j];
        #pragma unroll 8
        for (int i=0;i<128;i++) a = fmaf(hs[warp][i], __ldg(&nm_w2[i*64+j]), a);
        g_nu[(tok0+warp)*DD + j] = a;
    }
}

// ---------------------------------------------------------------------------
// Kernel 7: gate from reconstructed error. warp per token.
// ---------------------------------------------------------------------------
__global__ void __launch_bounds__(256) gate_kernel(){
    const int tid = threadIdx.x;
    const int warp = tid>>5, lane = tid&31;
    long tok = (long)blockIdx.x*8 + warp;
    float s = 0.f;
    #pragma unroll
    for (int h=0; h<2; h++){
        int c = lane + h*32;
        float v  = g_v[tok*DD + c];
        float pf = g_pqf[tok*DD + c];
        float ps = g_pqs[tok*DD + c];
        float e = v - 0.5f*(pf + ps);
        s += e*e;
    }
    const unsigned FULL = 0xffffffffu;
    #pragma unroll
    for (int d=1; d<32; d<<=1) s += __shfl_xor_sync(FULL,s,d);
    if (lane==0){
        g_gate[tok] = (s > 0.84729871f) ? 0.1f : 0.0f;
    }
}

// ---------------------------------------------------------------------------
// Kernel 8: ns scan + pw combine, unroll-8 with batched prefetch.
// ---------------------------------------------------------------------------
__global__ void __launch_bounds__(64,1) ns_kernel(){
    const int b = blockIdx.x;
    const int c = threadIdx.x;
    const long tb = (long)b*SS;
    float ns = 0.f;
    for (int tt=0; tt<SS; tt+=8){
        float gg[8], nn[8], of[8], os[8];
        float4 pw4[8];
        #pragma unroll
        for (int j=0;j<8;j++){
            long tok = tb + tt + j;
            gg[j] = g_gate[tok];
            nn[j] = g_nu[tok*DD + c];
            of[j] = g_outf[tok*DD + c];
            os[j] = g_outs[tok*DD + c];
            pw4[j] = *(const float4*)&g_pw[tok*4];
        }
        #pragma unroll
        for (int j=0;j<8;j++){
            ns = fmaf(gg[j], nn[j] - ns, ns);
            g_outpre[(tb+tt+j)*DD + c] =
                pw4[j].x*of[j] + pw4[j].y*os[j] + pw4[j].z*ns;
        }
    }
}

// ---------------------------------------------------------------------------
// Kernel 9: RMSNorm. warp per row.
// ---------------------------------------------------------------------------
__global__ void __launch_bounds__(256) rms_kernel(const float* __restrict__ norm_w){
    long row = (long)blockIdx.x*8 + (threadIdx.x>>5);
    int lane = threadIdx.x & 31;
    float x0 = g_outpre[row*DD + lane];
    float x1 = g_outpre[row*DD + 32 + lane];
    float ss = x0*x0 + x1*x1;
    #pragma unroll
    for (int d=1; d<32; d<<=1) ss += __shfl_xor_sync(0xffffffffu, ss, d);
    float inv = rsqrtf(ss*(1.0f/64.0f) + 1e-6f);
    g_a[row*DD + lane]      = x0*inv*norm_w[lane];
    g_a[row*DD + 32 + lane] = x1*inv*norm_w[32+lane];
}

// ---------------------------------------------------------------------------
// Kernel 10: out = g_a[8192,64] @ Wo[64,2048]. 64x64 tiles.
// ---------------------------------------------------------------------------
__global__ void __launch_bounds__(256,2) outgemm_kernel(
    const float* __restrict__ Wo, float* __restrict__ out)
{
    __shared__ __align__(16) float AsT[64][68];
    __shared__ __align__(16) float Bs[64][68];
    const int n0   = blockIdx.x*64;
    const int row0 = blockIdx.y*64;
    const int tid  = threadIdx.x;
    #pragma unroll
    for (int l=0;l<4;l++){
        int s = tid + l*256;
        int rr = s>>4, kq = s&15;
        float4 a4 = *(const float4*)&g_a[(long)(row0+rr)*DD + kq*4];
        AsT[kq*4+0][rr]=a4.x; AsT[kq*4+1][rr]=a4.y;
        AsT[kq*4+2][rr]=a4.z; AsT[kq*4+3][rr]=a4.w;
        float4 b4 = *(const float4*)&Wo[(long)rr*NN + n0 + kq*4];
        *(float4*)&Bs[rr][kq*4] = b4;
    }
    __syncthreads();
    const int tr = tid>>4, tc = tid&15;
    float acc[4][4];
    #pragma unroll
    for (int i=0;i<4;i++)
        #pragma unroll
        for (int j=0;j<4;j++) acc[i][j]=0.f;
    #pragma unroll 8
    for (int k=0;k<64;k++){
        float4 a4 = *(const float4*)&AsT[k][tr*4];
        float4 b4 = *(const float4*)&Bs[k][tc*4];
        float am[4]={a4.x,a4.y,a4.z,a4.w}, bn[4]={b4.x,b4.y,b4.z,b4.w};
        #pragma unroll
        for (int i=0;i<4;i++)
            #pragma unroll
            for (int j=0;j<4;j++) acc[i][j]=fmaf(am[i],bn[j],acc[i][j]);
    }
    #pragma unroll
    for (int i=0;i<4;i++){
        *(float4*)&out[(long)(row0+tr*4+i)*NN + n0 + tc*4] =
            make_float4(acc[i][0],acc[i][1],acc[i][2],acc[i][3]);
    }
}

extern "C" void kernel_launch(void* const* d_in, const int* in_sizes, int n_in,
                              void* d_out, int out_size)
{
    const float* x      = (const float*)d_in[0];
    const float* Wk     = (const float*)d_in[1];
    const float* Wv     = (const float*)d_in[2];
    const float* Wq     = (const float*)d_in[3];
    const float* fa     = (const float*)d_in[4];
    const float* sa     = (const float*)d_in[5];
    const float* nm_w1  = (const float*)d_in[6];
    const float* nm_b1  = (const float*)d_in[7];
    const float* nm_w2  = (const float*)d_in[8];
    const float* nm_b2  = (const float*)d_in[9];
    const float* ir_w1  = (const float*)d_in[10];
    const float* ir_b1  = (const float*)d_in[11];
    const float* ir_w2  = (const float*)d_in[12];
    const float* ir_b2  = (const float*)d_in[13];
    const float* pw_w   = (const float*)d_in[14];
    const float* pw_b   = (const float*)d_in[15];
    const float* Wo     = (const float*)d_in[16];
    const float* norm_w = (const float*)d_in[17];
    float* out = (float*)d_out;

    // projmma at launch index 3 for the ncu capture slot.
    splitx_kernel<<<16384, 256>>>(x);
    splitw_kernel<<<128, 256>>>(Wk, Wv, Wq, ir_w1);
    pw_kernel<<<128, 256>>>(x, pw_w, pw_b);
    projmma_kernel<<<dim3(64,4), 256>>>();
    irgate_kernel<<<1024, 256>>>(ir_b1, ir_w2, ir_b2);
    chunkdots_kernel<<<NCHT, 256>>>();
    prep_kernel<<<dim3(NCHT,2), 64>>>(fa, sa);
    scan_chunk_kernel<<<dim3(16,BB,2), 256>>>(fa, sa);
    nu_kernel<<<1024, 256>>>(nm_w1, nm_b1, nm_w2, nm_b2);
    gate_kernel<<<1024, 256>>>();
    ns_kernel<<<4, 64>>>();
    rms_kernel<<<1024, 256>>>(norm_w);
    outgemm_kernel<<<dim3(32,128), 256>>>(Wo, out);
}

// round 16
// speedup vs baseline: 1.3898x; 1.0030x over previous
#include <cuda_runtime.h>
#include <cuda_bf16.h>
#include <math.h>

#define BB 4
#define SS 2048
#define DD 64
#define NN 2048
#define NTOK (BB*SS)
#define CT 64
#define NCH (SS/CT)
#define NCHT (BB*NCH)

// -------- static device scratch (no allocations allowed) ----------
__device__ float g_k[NTOK*DD];
__device__ float g_q[NTOK*DD];
__device__ float g_v[NTOK*DD];
__device__ float g_h1[NTOK*DD];
__device__ float g_nu[NTOK*DD];
__device__ float g_pw[NTOK*4];
__device__ float g_us[NTOK];
__device__ float g_outf[NTOK*DD];
__device__ float g_outs[NTOK*DD];
__device__ float g_pqf[NTOK*DD];
__device__ float g_pqs[NTOK*DD];
__device__ float g_kk[NCHT*CT*CT];
__device__ float g_qx[NCHT*CT*CT];
__device__ float g_W [2*NCHT*CT*CT];
__device__ float g_A2[2*NCHT*CT*CT];
__device__ float g_gate[NTOK];
__device__ float g_outpre[NTOK*DD];
__device__ float g_a[NTOK*DD];
// bf16 split operands
__device__ __nv_bfloat16 g_xh[NTOK*NN];
__device__ __nv_bfloat16 g_xl[NTOK*NN];
__device__ __nv_bfloat16 g_wth[4*DD*NN];   // [seg][n][k]
__device__ __nv_bfloat16 g_wtl[4*DD*NN];

__device__ __forceinline__ float gelu_exact(float x){
    return 0.5f*x*(1.0f + erff(x*0.70710678118654752f));
}
__device__ __forceinline__ float dot4(float4 a, float4 b){
    return a.x*b.x + a.y*b.y + a.z*b.z + a.w*b.w;
}
__device__ __forceinline__ void mma16816(float* c, const unsigned* a, const unsigned* b){
    asm volatile(
        "mma.sync.aligned.m16n8k16.row.col.f32.bf16.bf16.f32 "
        "{%0,%1,%2,%3}, {%4,%5,%6,%7}, {%8,%9}, {%0,%1,%2,%3};"
        : "+f"(c[0]), "+f"(c[1]), "+f"(c[2]), "+f"(c[3])
        : "r"(a[0]), "r"(a[1]), "r"(a[2]), "r"(a[3]), "r"(b[0]), "r"(b[1]));
}
__device__ __forceinline__ unsigned pack2(__nv_bfloat16 a, __nv_bfloat16 b){
    return ((unsigned)__bfloat16_as_ushort(b) << 16) | (unsigned)__bfloat16_as_ushort(a);
}

// ---------------------------------------------------------------------------
// Kernel 0a: split x into bf16 hi/lo. 16384 blocks x 256 thr, float4/thread.
// ---------------------------------------------------------------------------
__global__ void __launch_bounds__(256) splitx_kernel(const float* __restrict__ x){
    long i4 = (long)blockIdx.x*256 + threadIdx.x;
    float4 v = ((const float4*)x)[i4];
    float f[4] = {v.x, v.y, v.z, v.w};
    __nv_bfloat16 h[4], l[4];
    #pragma unroll
    for (int j=0;j<4;j++){
        h[j] = __float2bfloat16(f[j]);
        l[j] = __float2bfloat16(f[j] - __bfloat162float(h[j]));
    }
    *(uint2*)&g_xh[i4*4] = make_uint2(pack2(h[0],h[1]), pack2(h[2],h[3]));
    *(uint2*)&g_xl[i4*4] = make_uint2(pack2(l[0],l[1]), pack2(l[2],l[3]));
}

// ---------------------------------------------------------------------------
// Kernel 0b: transpose + split the 4 projection weights into [seg][n][k] bf16.
// grid 128 (4 segs x 32 k-tiles), 256 thr, smem transpose.
// ---------------------------------------------------------------------------
__global__ void __launch_bounds__(256) splitw_kernel(
    const float* __restrict__ Wk, const float* __restrict__ Wv,
    const float* __restrict__ Wq, const float* __restrict__ Wi)
{
    __shared__ float T[64][65];
    const int seg = blockIdx.x >> 5;
    const int k0  = (blockIdx.x & 31) * 64;
    const float* __restrict__ W = (seg==0)?Wk:(seg==1)?Wv:(seg==2)?Wq:Wi;
    const int tid = threadIdx.x;
    #pragma unroll
    for (int l=0;l<4;l++){
        int i4 = tid + l*256;
        int kr = i4 >> 4, c4 = (i4 & 15)*4;
        float4 w = *(const float4*)&W[(long)(k0+kr)*DD + c4];
        T[kr][c4+0]=w.x; T[kr][c4+1]=w.y; T[kr][c4+2]=w.z; T[kr][c4+3]=w.w;
    }
    __syncthreads();
    #pragma unroll
    for (int l=0;l<4;l++){
        int idx = tid + l*256;
        int n = idx >> 4, kc = (idx & 15)*4;
        __nv_bfloat16 h[4], lo[4];
        #pragma unroll
        for (int j=0;j<4;j++){
            float f = T[kc+j][n];
            h[j]  = __float2bfloat16(f);
            lo[j] = __float2bfloat16(f - __bfloat162float(h[j]));
        }
        long dst = ((long)seg*DD + n)*NN + k0 + kc;
        *(uint2*)&g_wth[dst] = make_uint2(pack2(h[0],h[1]),  pack2(h[2],h[3]));
        *(uint2*)&g_wtl[dst] = make_uint2(pack2(lo[0],lo[1]), pack2(lo[2],lo[3]));
    }
}

// ---------------------------------------------------------------------------
// Kernel 1: tensor-core projections via split-bf16 mma, pre-split operands.
// grid (64 row-tiles, 4 segments), 256 thr. Tile 128x64, KC=32 (smem 30 KB).
// seg0 k=l2norm, seg1 v, seg2 q=l2norm, seg3 h1 (raw fp32, gate done later).
// ---------------------------------------------------------------------------
#define KC 32
#define ASTR 40
__global__ void __launch_bounds__(256,2) projmma_kernel(){
    __shared__ __align__(16) __nv_bfloat16 Ah[128][ASTR];
    __shared__ __align__(16) __nv_bfloat16 Al[128][ASTR];
    __shared__ __align__(16) __nv_bfloat16 Bh[64][ASTR];
    __shared__ __align__(16) __nv_bfloat16 Bl[64][ASTR];

    const int seg  = blockIdx.y;
    const int row0 = blockIdx.x * 128;
    const int tid  = threadIdx.x;
    const int warp = tid >> 5;
    const int lane = tid & 31;
    const int g = lane >> 2;
    const int t = lane & 3;
    const int wrow = warp * 16;

    float C[8][4];
    #pragma unroll
    for (int n=0;n<8;n++)
        #pragma unroll
        for (int j=0;j<4;j++) C[n][j]=0.f;

    for (int kb = 0; kb < NN; kb += KC){
        // stage x tile: 128 rows x 32 cols = 512 f8 per buffer (pure copies)
        #pragma unroll
        for (int l=0;l<2;l++){
            int idx = tid + l*256;
            int row = idx >> 2, c8 = (idx & 3)*8;
            long src = (long)(row0+row)*NN + kb + c8;
            *(float4*)&Ah[row][c8] = *(const float4*)&g_xh[src];
            *(float4*)&Al[row][c8] = *(const float4*)&g_xl[src];
        }
        // stage W tile: 64 rows x 32 cols = 256 f8 per buffer
        {
            int idx = tid;
            int row = idx >> 2, c8 = (idx & 3)*8;
            long src = ((long)seg*DD + row)*NN + kb + c8;
            *(float4*)&Bh[row][c8] = *(const float4*)&g_wth[src];
            *(float4*)&Bl[row][c8] = *(const float4*)&g_wtl[src];
        }
        __syncthreads();

        #pragma unroll
        for (int ks=0; ks<2; ks++){
            const int k16 = ks*16;
            unsigned ahf[4], alf[4];
            ahf[0] = *(const unsigned*)&Ah[wrow+g  ][k16+t*2];
            ahf[1] = *(const unsigned*)&Ah[wrow+g+8][k16+t*2];
            ahf[2] = *(const unsigned*)&Ah[wrow+g  ][k16+8+t*2];
            ahf[3] = *(const unsigned*)&Ah[wrow+g+8][k16+8+t*2];
            alf[0] = *(const unsigned*)&Al[wrow+g  ][k16+t*2];
            alf[1] = *(const unsigned*)&Al[wrow+g+8][k16+t*2];
            alf[2] = *(const unsigned*)&Al[wrow+g  ][k16+8+t*2];
            alf[3] = *(const unsigned*)&Al[wrow+g+8][k16+8+t*2];
            #pragma unroll
            for (int nt=0; nt<8; nt++){
                const int n = nt*8 + g;
                unsigned bhf[2], blf[2];
                bhf[0] = *(const unsigned*)&Bh[n][k16+t*2];
                bhf[1] = *(const unsigned*)&Bh[n][k16+8+t*2];
                blf[0] = *(const unsigned*)&Bl[n][k16+t*2];
                blf[1] = *(const unsigned*)&Bl[n][k16+8+t*2];
                mma16816(C[nt], ahf, bhf);
                mma16816(C[nt], ahf, blf);
                mma16816(C[nt], alf, bhf);
            }
        }
        __syncthreads();
    }

    float* dst = (seg==0)? g_k : (seg==1)? g_v : (seg==2)? g_q : g_h1;
    const long rlo = row0 + wrow + g;
    const long rhi = rlo + 8;
    if (seg == 1 || seg == 3){
        #pragma unroll
        for (int nt=0; nt<8; nt++){
            *(float2*)&dst[rlo*DD + nt*8 + t*2] = make_float2(C[nt][0], C[nt][1]);
            *(float2*)&dst[rhi*DD + nt*8 + t*2] = make_float2(C[nt][2], C[nt][3]);
        }
    } else {
        float sl = 0.f, sh = 0.f;
        #pragma unroll
        for (int nt=0; nt<8; nt++){
            sl += C[nt][0]*C[nt][0] + C[nt][1]*C[nt][1];
            sh += C[nt][2]*C[nt][2] + C[nt][3]*C[nt][3];
        }
        const unsigned FULL = 0xffffffffu;
        sl += __shfl_xor_sync(FULL, sl, 1); sl += __shfl_xor_sync(FULL, sl, 2);
        sh += __shfl_xor_sync(FULL, sh, 1); sh += __shfl_xor_sync(FULL, sh, 2);
        float il = 1.0f / fmaxf(sqrtf(sl), 1e-12f);
        float ih = 1.0f / fmaxf(sqrtf(sh), 1e-12f);
        #pragma unroll
        for (int nt=0; nt<8; nt++){
            *(float2*)&dst[rlo*DD + nt*8 + t*2] = make_float2(C[nt][0]*il, C[nt][1]*il);
            *(float2*)&dst[rhi*DD + nt*8 + t*2] = make_float2(C[nt][2]*ih, C[nt][3]*ih);
        }
    }
}

// ---------------------------------------------------------------------------
// Kernel 1c: importance gate from h1 (fp32 gelu + dot + threshold). warp/token.
// ---------------------------------------------------------------------------
__global__ void __launch_bounds__(256) irgate_kernel(
    const float* __restrict__ ir_b1, const float* __restrict__ ir_w2,
    const float* __restrict__ ir_b2)
{
    const int warp = threadIdx.x >> 5, lane = threadIdx.x & 31;
    long tok = (long)blockIdx.x*8 + warp;
    float p = gelu_exact(g_h1[tok*DD + lane]      + ir_b1[lane])      * ir_w2[lane]
            + gelu_exact(g_h1[tok*DD + 32 + lane] + ir_b1[32+lane])   * ir_w2[32+lane];
    const unsigned FULL = 0xffffffffu;
    #pragma unroll
    for (int d=1; d<32; d<<=1) p += __shfl_xor_sync(FULL, p, d);
    if (lane==0) g_us[tok] = (p + ir_b2[0]) > 0.f ? 1.f : 0.f;
}

// ---------------------------------------------------------------------------
// Kernel 2: per-chunk Gram matrices.
// ---------------------------------------------------------------------------
__global__ void __launch_bounds__(256) chunkdots_kernel(){
    __shared__ __align__(16) float Ks[CT][68];
    __shared__ __align__(16) float Qs[CT][68];
    const int p = blockIdx.x;
    const long t0 = (long)p*CT;
    const int tid = threadIdx.x;
    const float4* kp = (const float4*)(g_k + t0*DD);
    const float4* qp = (const float4*)(g_q + t0*DD);
    #pragma unroll
    for (int l=0;l<4;l++){
        int f4 = tid + l*256;
        int row = f4 >> 4, col = (f4 & 15)*4;
        *(float4*)&Ks[row][col] = kp[f4];
        *(float4*)&Qs[row][col] = qp[f4];
    }
    __syncthreads();
    #pragma unroll
    for (int m=0;m<16;m++){
        int idx = tid + m*256;
        int i = idx >> 6, j = idx & 63;
        float sk = 0.f, sq = 0.f;
        #pragma unroll
        for (int r4=0;r4<16;r4++){
            float4 kj = *(float4*)&Ks[j][r4*4];
            float4 ki = *(float4*)&Ks[i][r4*4];
            float4 qi = *(float4*)&Qs[i][r4*4];
            sk += dot4(ki,kj);
            sq += dot4(qi,kj);
        }
        g_kk[(long)p*4096 + idx] = sk;
        g_qx[(long)p*4096 + idx] = sq;
    }
}

// ---------------------------------------------------------------------------
// Kernel 3: per chunk-state: build L, invert (I+L) -> W, build A2.
// ---------------------------------------------------------------------------
__global__ void __launch_bounds__(64) prep_kernel(
    const float* __restrict__ fa_p, const float* __restrict__ sa_p)
{
    __shared__ float L[CT][65];
    __shared__ float W[CT][65];
    __shared__ float apow[CT];
    __shared__ float gi[CT];
    const int p = blockIdx.x;
    const int st = blockIdx.y;
    const long t0 = (long)p*CT;
    const int tid = threadIdx.x;
    const float a = st ? *sa_p : *fa_p;
    const float oa = 1.0f - a;
    if (tid == 0){
        float w = 1.f;
        for (int i=0;i<CT;i++){ apow[i] = w; w *= a; }
    }
    gi[tid] = st ? oa*g_us[t0+tid] : oa;
    __syncthreads();
    const long base = (long)p*4096;
    const long obase = ((long)st*NCHT + p)*4096;
    for (int f = tid; f < 4096; f += 64){
        int i = f >> 6, j = f & 63;
        float dec = (j < i) ? apow[i-1-j] : 0.f;
        L[i][j] = dec * gi[i] * g_kk[base+f];
        g_A2[obase+f] = dec * g_qx[base+f];
    }
    __syncthreads();
    {
        const int j = tid;
        for (int i=0;i<CT;i++) W[i][j] = (i==j) ? 1.f : 0.f;
        for (int i=j+1;i<CT;i++){
            float s = 0.f;
            for (int k=j;k<i;k++) s = fmaf(L[i][k], W[k][j], s);
            W[i][j] = -s;
        }
    }
    __syncthreads();
    for (int f = tid; f < 4096; f += 64)
        g_W[obase+f] = W[f>>6][f&63];
}

// ---------------------------------------------------------------------------
// Kernel 4: chunked scan. grid (16, 4, 2), 256 thr.
// ---------------------------------------------------------------------------
__global__ void __launch_bounds__(256,1) scan_chunk_kernel(
    const float* __restrict__ fa_p, const float* __restrict__ sa_p)
{
    __shared__ __align__(16) float Ks[CT][68];
    __shared__ __align__(16) float Ss[CT][68];
    __shared__ __align__(16) float H [4][68];
    __shared__ __align__(16) float T1[4][68];
    __shared__ __align__(16) float Cc[4][68];
    __shared__ __align__(16) float QHs[4][68];
    __shared__ float apow[CT];

    const int cg = blockIdx.x;
    const int b  = blockIdx.y;
    const int st = blockIdx.z;
    const int tid = threadIdx.x;
    const int i = tid >> 2;
    const int c = tid & 3;
    const int colg = cg*4 + c;
    const float a = st ? *sa_p : *fa_p;
    const float oa = 1.0f - a;
    float* __restrict__ outp = st ? g_outs : g_outf;
    float* __restrict__ pqp  = st ? g_pqs  : g_pqf;

    if (tid == 0){
        float w = 1.f;
        for (int t=0;t<CT;t++){ apow[t] = w; w *= a; }
    }
    H[c][i] = 0.f;
    __syncthreads();
    const float a64 = apow[63]*a;

    for (int ch = 0; ch < NCH; ch++){
        const int  pidx = b*NCH + ch;
        const long t0   = (long)pidx*CT;
        const long wbase = ((long)st*NCHT + pidx)*4096;

        {
            const float4* kp = (const float4*)(g_k + t0*DD);
            const float4* qp = (const float4*)(g_q + t0*DD);
            #pragma unroll
            for (int l=0;l<4;l++){
                int f4 = tid + l*256;
                int row = f4 >> 4, col = (f4 & 15)*4;
                *(float4*)&Ks[row][col] = kp[f4];
                *(float4*)&Ss[row][col] = qp[f4];
            }
        }
        __syncthreads();

        {
            float akh = 0.f, aqh = 0.f;
            #pragma unroll
            for (int r4=0;r4<16;r4++){
                float4 h4 = *(float4*)&H [c][r4*4];
                float4 k4 = *(float4*)&Ks[i][r4*4];
                float4 q4 = *(float4*)&Ss[i][r4*4];
                akh += dot4(k4,h4);
                aqh += dot4(q4,h4);
            }
            float giv = st ? oa*g_us[t0+i] : oa;
            float v   = g_v[(t0+i)*DD + colg];
            T1[c][i]  = giv*(v - apow[i]*akh);
            QHs[c][i] = aqh;
        }
        __syncthreads();

        {
            const float4* wp = (const float4*)(g_W + wbase);
            #pragma unroll
            for (int l=0;l<4;l++){
                int f4 = tid + l*256;
                int row = f4 >> 4, col = (f4 & 15)*4;
                *(float4*)&Ss[row][col] = wp[f4];
            }
        }
        __syncthreads();

        {
            float s = 0.f;
            #pragma unroll
            for (int j4=0;j4<16;j4++){
                float4 w4 = *(float4*)&Ss[i][j4*4];
                float4 r4 = *(float4*)&T1[c][j4*4];
                s += dot4(w4,r4);
            }
            Cc[c][i] = s;
        }
        __syncthreads();

        {
            const float4* ap = (const float4*)(g_A2 + wbase);
            #pragma unroll
            for (int l=0;l<4;l++){
                int f4 = tid + l*256;
                int row = f4 >> 4, col = (f4 & 15)*4;
                *(float4*)&Ss[row][col] = ap[f4];
            }
        }
        __syncthreads();

        {
            float s = 0.f;
            #pragma unroll
            for (int j4=0;j4<16;j4++){
                float4 a4 = *(float4*)&Ss[i][j4*4];
                float4 c4 = *(float4*)&Cc[c][j4*4];
                s += dot4(a4,c4);
            }
            float ci = Cc[c][i];
            float pq = fmaf(apow[i], QHs[c][i], s);
            float qk = g_qx[(long)pidx*4096 + i*65];
            float o  = fmaf(qk, ci, a*pq);
            pqp [(t0+i)*DD + colg] = pq;
            outp[(t0+i)*DD + colg] = o;
            T1[c][i] = apow[63-i]*ci;
        }
        __syncthreads();

        {
            float h = a64*H[c][i];
            #pragma unroll
            for (int j=0;j<CT;j++)
                h = fmaf(Ks[j][i], T1[c][j], h);
            H[c][i] = h;
        }
        __syncthreads();
    }
}

// ---------------------------------------------------------------------------
// Kernel 5: pw = softmax(x @ pw_w + pw_b). warp per token.
// ---------------------------------------------------------------------------
__global__ void __launch_bounds__(256) pw_kernel(
    const float* __restrict__ x, const float* __restrict__ pw_w,
    const float* __restrict__ pw_b)
{
    __shared__ __align__(16) float pwT[3][2048];
    const int tid = threadIdx.x;
    for (int idx = tid; idx < 3*2048; idx += 256){
        int i = idx/3, cc = idx - i*3;
        pwT[cc][i] = pw_w[idx];
    }
    __syncthreads();
    const int warp = tid>>5, lane = tid&31;
    const float b0 = pw_b[0], b1 = pw_b[1], b2 = pw_b[2];
    const unsigned FULL = 0xffffffffu;
    for (int it8 = 0; it8 < 8; it8++){
        long tok = (long)blockIdx.x*64 + warp*8 + it8;
        const float* xr = x + tok*NN;
        float a0=0.f,a1=0.f,a2=0.f;
        #pragma unroll
        for (int it=0; it<16; it++){
            int off = it*128 + lane*4;
            float4 xv = *(const float4*)&xr[off];
            float4 w0 = *(const float4*)&pwT[0][off];
            float4 w1 = *(const float4*)&pwT[1][off];
            float4 w2 = *(const float4*)&pwT[2][off];
            a0 += dot4(xv,w0);
            a1 += dot4(xv,w1);
            a2 += dot4(xv,w2);
        }
        #pragma unroll
        for (int d=1; d<32; d<<=1){
            a0 += __shfl_xor_sync(FULL, a0, d);
            a1 += __shfl_xor_sync(FULL, a1, d);
            a2 += __shfl_xor_sync(FULL, a2, d);
        }
        if (lane==0){
            float l0=a0+b0, l1=a1+b1, l2=a2+b2;
            float m = fmaxf(l0, fmaxf(l1,l2));
            float e0=expf(l0-m), e1=expf(l1-m), e2=expf(l2-m);
            float inv = 1.0f/(e0+e1+e2);
            g_pw[tok*4+0]=e0*inv; g_pw[tok*4+1]=e1*inv;
            g_pw[tok*4+2]=e2*inv; g_pw[tok*4+3]=0.f;
        }
    }
}

// ---------------------------------------------------------------------------
// Kernel 6: nu = gelu(v @ nm_w1 + b1) @ nm_w2 + b2. warp per token.
// ---------------------------------------------------------------------------
__global__ void __launch_bounds__(256) nu_kernel(
    const float* __restrict__ nm_w1, const float* __restrict__ nm_b1,
    const float* __restrict__ nm_w2, const float* __restrict__ nm_b2)
{
    __shared__ float W1s[64*128];
    __shared__ float hs[8][128];
    __shared__ float vs[8][64];
    const int tid = threadIdx.x;
    for (int i = tid; i < 64*128; i += 256) W1s[i] = nm_w1[i];
    long tok0 = (long)blockIdx.x*8;
    for (int i = tid; i < 8*64; i += 256){
        int t = i>>6, r = i&63;
        vs[t][r] = g_v[(tok0+t)*DD + r];
    }
    __syncthreads();
    const int warp = tid>>5, lane = tid&31;
    #pragma unroll
    for (int ii=0;ii<4;ii++){
        int i = lane + ii*32;
        float a = nm_b1[i];
        #pragma unroll 8
        for (int r=0;r<64;r++) a = fmaf(vs[warp][r], W1s[r*128+i], a);
        hs[warp][i] = gelu_exact(a);
    }
    __syncwarp();
    #pragma unroll
    for (int jj=0;jj<2;jj++){
        int j = lane + jj*32;
        float a = nm_b2[j];
        #pragma unroll 8
        for (int i=0;i<128;i++) a = fmaf(hs[warp][i], __ldg(&nm_w2[i*64+j]), a);
        g_nu[(tok0+warp)*DD + j] = a;
    }
}

// ---------------------------------------------------------------------------
// Kernel 7: gate from reconstructed error. warp per token.
// ---------------------------------------------------------------------------
__global__ void __launch_bounds__(256) gate_kernel(){
    const int tid = threadIdx.x;
    const int warp = tid>>5, lane = tid&31;
    long tok = (long)blockIdx.x*8 + warp;
    float s = 0.f;
    #pragma unroll
    for (int h=0; h<2; h++){
        int c = lane + h*32;
        float v  = g_v[tok*DD + c];
        float pf = g_pqf[tok*DD + c];
        float ps = g_pqs[tok*DD + c];
        float e = v - 0.5f*(pf + ps);
        s += e*e;
    }
    const unsigned FULL = 0xffffffffu;
    #pragma unroll
    for (int d=1; d<32; d<<=1) s += __shfl_xor_sync(FULL,s,d);
    if (lane==0){
        g_gate[tok] = (s > 0.84729871f) ? 0.1f : 0.0f;
    }
}

// ---------------------------------------------------------------------------
// Kernel 8: ns scan + pw combine, unroll-8 with batched prefetch.
// ---------------------------------------------------------------------------
__global__ void __launch_bounds__(64,1) ns_kernel(){
    const int b = blockIdx.x;
    const int c = threadIdx.x;
    const long tb = (long)b*SS;
    float ns = 0.f;
    for (int tt=0; tt<SS; tt+=8){
        float gg[8], nn[8], of[8], os[8];
        float4 pw4[8];
        #pragma unroll
        for (int j=0;j<8;j++){
            long tok = tb + tt + j;
            gg[j] = g_gate[tok];
            nn[j] = g_nu[tok*DD + c];
            of[j] = g_outf[tok*DD + c];
            os[j] = g_outs[tok*DD + c];
            pw4[j] = *(const float4*)&g_pw[tok*4];
        }
        #pragma unroll
        for (int j=0;j<8;j++){
            ns = fmaf(gg[j], nn[j] - ns, ns);
            g_outpre[(tb+tt+j)*DD + c] =
                pw4[j].x*of[j] + pw4[j].y*os[j] + pw4[j].z*ns;
        }
    }
}

// ---------------------------------------------------------------------------
// Kernel 9: RMSNorm. warp per row.
// ---------------------------------------------------------------------------
__global__ void __launch_bounds__(256) rms_kernel(const float* __restrict__ norm_w){
    long row = (long)blockIdx.x*8 + (threadIdx.x>>5);
    int lane = threadIdx.x & 31;
    float x0 = g_outpre[row*DD + lane];
    float x1 = g_outpre[row*DD + 32 + lane];
    float ss = x0*x0 + x1*x1;
    #pragma unroll
    for (int d=1; d<32; d<<=1) ss += __shfl_xor_sync(0xffffffffu, ss, d);
    float inv = rsqrtf(ss*(1.0f/64.0f) + 1e-6f);
    g_a[row*DD + lane]      = x0*inv*norm_w[lane];
    g_a[row*DD + 32 + lane] = x1*inv*norm_w[32+lane];
}

// ---------------------------------------------------------------------------
// Kernel 10: out = g_a[8192,64] @ Wo[64,2048]. 64x64 tiles.
// ---------------------------------------------------------------------------
__global__ void __launch_bounds__(256,2) outgemm_kernel(
    const float* __restrict__ Wo, float* __restrict__ out)
{
    __shared__ __align__(16) float AsT[64][68];
    __shared__ __align__(16) float Bs[64][68];
    const int n0   = blockIdx.x*64;
    const int row0 = blockIdx.y*64;
    const int tid  = threadIdx.x;
    #pragma unroll
    for (int l=0;l<4;l++){
        int s = tid + l*256;
        int rr = s>>4, kq = s&15;
        float4 a4 = *(const float4*)&g_a[(long)(row0+rr)*DD + kq*4];
        AsT[kq*4+0][rr]=a4.x; AsT[kq*4+1][rr]=a4.y;
        AsT[kq*4+2][rr]=a4.z; AsT[kq*4+3][rr]=a4.w;
        float4 b4 = *(const float4*)&Wo[(long)rr*NN + n0 + kq*4];
        *(float4*)&Bs[rr][kq*4] = b4;
    }
    __syncthreads();
    const int tr = tid>>4, tc = tid&15;
    float acc[4][4];
    #pragma unroll
    for (int i=0;i<4;i++)
        #pragma unroll
        for (int j=0;j<4;j++) acc[i][j]=0.f;
    #pragma unroll 8
    for (int k=0;k<64;k++){
        float4 a4 = *(const float4*)&AsT[k][tr*4];
        float4 b4 = *(const float4*)&Bs[k][tc*4];
        float am[4]={a4.x,a4.y,a4.z,a4.w}, bn[4]={b4.x,b4.y,b4.z,b4.w};
        #pragma unroll
        for (int i=0;i<4;i++)
            #pragma unroll
            for (int j=0;j<4;j++) acc[i][j]=fmaf(am[i],bn[j],acc[i][j]);
    }
    #pragma unroll
    for (int i=0;i<4;i++){
        *(float4*)&out[(long)(row0+tr*4+i)*NN + n0 + tc*4] =
            make_float4(acc[i][0],acc[i][1],acc[i][2],acc[i][3]);
    }
}

extern "C" void kernel_launch(void* const* d_in, const int* in_sizes, int n_in,
                              void* d_out, int out_size)
{
    const float* x      = (const float*)d_in[0];
    const float* Wk     = (const float*)d_in[1];
    const float* Wv     = (const float*)d_in[2];
    const float* Wq     = (const float*)d_in[3];
    const float* fa     = (const float*)d_in[4];
    const float* sa     = (const float*)d_in[5];
    const float* nm_w1  = (const float*)d_in[6];
    const float* nm_b1  = (const float*)d_in[7];
    const float* nm_w2  = (const float*)d_in[8];
    const float* nm_b2  = (const float*)d_in[9];
    const float* ir_w1  = (const float*)d_in[10];
    const float* ir_b1  = (const float*)d_in[11];
    const float* ir_w2  = (const float*)d_in[12];
    const float* ir_b2  = (const float*)d_in[13];
    const float* pw_w   = (const float*)d_in[14];
    const float* pw_b   = (const float*)d_in[15];
    const float* Wo     = (const float*)d_in[16];
    const float* norm_w = (const float*)d_in[17];
    float* out = (float*)d_out;

    // projmma at launch index 3 for the ncu capture slot.
    splitx_kernel<<<16384, 256>>>(x);
    splitw_kernel<<<128, 256>>>(Wk, Wv, Wq, ir_w1);
    pw_kernel<<<128, 256>>>(x, pw_w, pw_b);
    projmma_kernel<<<dim3(64,4), 256>>>();
    irgate_kernel<<<1024, 256>>>(ir_b1, ir_w2, ir_b2);
    chunkdots_kernel<<<NCHT, 256>>>();
    prep_kernel<<<dim3(NCHT,2), 64>>>(fa, sa);
    scan_chunk_kernel<<<dim3(16,BB,2), 256>>>(fa, sa);
    nu_kernel<<<1024, 256>>>(nm_w1, nm_b1, nm_w2, nm_b2);
    gate_kernel<<<1024, 256>>>();
    ns_kernel<<<4, 64>>>();
    rms_kernel<<<1024, 256>>>(norm_w);
    outgemm_kernel<<<dim3(32,128), 256>>>(Wo, out);
}